// round 5
// baseline (speedup 1.0000x reference)
#include <cuda_runtime.h>
#include <math.h>

#define BZ   16
#define SEQ  512
#define DM   1024
#define NH   8
#define DH   128
#define SKM  513          // keys with memory token
#define SLD  516          // scores leading dim (mult of 4 for float4)
#define N3   3072

// ---------------- static scratch (device globals; allocation-free) ----------
__device__ float g_mean[2][BZ][DM];                 // 0: v_mean, 1: q_mean
__device__ float g_gate[2][BZ][DM];                 // 0: 1+q4v_gate (for v), 1: 1+v4q_gate (for q)
__device__ float g_K[3][BZ][SEQ + 1][DM];
__device__ float g_Q[3][BZ][SEQ][DM];
__device__ float g_V[3][BZ][SEQ + 1][DM];
__device__ float g_S[BZ * NH][SEQ][SLD];            // scores scratch, reused per modality
__device__ float g_U[BZ][SEQ][DM];                  // attention update, reused per modality

// ---------------- masked mean ----------------
__global__ void mean_kernel(const float* __restrict__ x, const float* __restrict__ mask, int slot) {
    int b = blockIdx.x;
    __shared__ float sm[SEQ];
    __shared__ float smsum;
    for (int i = threadIdx.x; i < SEQ; i += blockDim.x) sm[i] = mask[b * SEQ + i];
    __syncthreads();
    if (threadIdx.x == 0) {
        float s = 0.f;
        for (int i = 0; i < SEQ; i++) s += sm[i];
        smsum = s;
    }
    __syncthreads();
    float inv = 1.f / smsum;
    for (int d = threadIdx.x; d < DM; d += blockDim.x) {
        float acc = 0.f;
        for (int i = 0; i < SEQ; i++) acc += x[(b * SEQ + i) * DM + d] * sm[i];
        g_mean[slot][b][d] = acc * inv;
    }
}

// ---------------- gate = 1 + sigmoid(relu(mean) @ w + b) ----------------
__global__ void gate_kernel(int mean_slot, const float* __restrict__ w,
                            const float* __restrict__ bias, int gate_slot) {
    int b = blockIdx.y;
    int d = blockIdx.x * 128 + threadIdx.x;
    __shared__ float sm[DM];
    for (int k = threadIdx.x; k < DM; k += 128) sm[k] = fmaxf(g_mean[mean_slot][b][k], 0.f);
    __syncthreads();
    float acc = bias[d];
    for (int k = 0; k < DM; k++) acc = fmaf(sm[k], w[k * DM + d], acc);
    g_gate[gate_slot][b][d] = 1.f + 1.f / (1.f + expf(-acc));
}

// ---------------- memory tokens (row 0 of K/V for v and c) ----------------
__global__ void memtok_kernel(const float* __restrict__ mvk, const float* __restrict__ mvv,
                              const float* __restrict__ mck, const float* __restrict__ mcv) {
    int b = blockIdx.y;
    int d = blockIdx.x * 128 + threadIdx.x;
    float gv = g_gate[0][b][d];                 // (1+q4v_gate) applies to v_k incl. memory token
    g_K[0][b][0][d] = 32.f * mvk[d] * gv;       // sqrt(1024) = 32
    g_V[0][b][0][d] = mvv[d];
    g_K[2][b][0][d] = 32.f * mck[d];            // c is not gated
    g_V[2][b][0][d] = mcv[d];
}

// ---------------- trans GEMM: (relu(X) @ W + b) * mask, split K/Q/V, gate ----
// M = BZ*SEQ = 8192, N = 3072, K = 1024. 128x128 tile, BK=16, 256 thr, 8x8 micro.
__global__ void __launch_bounds__(256) trans_gemm(
    const float* __restrict__ A, const float* __restrict__ W,
    const float* __restrict__ bias, const float* __restrict__ mask,
    int mod, int gated, int rowoff) {
    int mtile = blockIdx.y * 128;
    int ntile = blockIdx.x * 128;
    int tid = threadIdx.x;
    int tr = tid >> 4, tc = tid & 15;
    __shared__ __align__(16) float As[16][128];
    __shared__ __align__(16) float Bs[16][128];
    float acc[8][8] = {};
    for (int k0 = 0; k0 < DM; k0 += 16) {
#pragma unroll
        for (int l = 0; l < 2; l++) {
            int idx = tid + l * 256;
            int row = idx >> 2;
            int kk = (idx & 3) * 4;
            float4 v = *(const float4*)(A + (size_t)(mtile + row) * DM + k0 + kk);
            As[kk + 0][row] = fmaxf(v.x, 0.f);
            As[kk + 1][row] = fmaxf(v.y, 0.f);
            As[kk + 2][row] = fmaxf(v.z, 0.f);
            As[kk + 3][row] = fmaxf(v.w, 0.f);
        }
#pragma unroll
        for (int l = 0; l < 2; l++) {
            int idx = tid + l * 256;
            int row = idx >> 5;
            int cc = (idx & 31) * 4;
            *(float4*)&Bs[row][cc] = *(const float4*)(W + (size_t)(k0 + row) * N3 + ntile + cc);
        }
        __syncthreads();
#pragma unroll
        for (int k = 0; k < 16; k++) {
            float4 a0 = *(const float4*)&As[k][tr * 8];
            float4 a1 = *(const float4*)&As[k][tr * 8 + 4];
            float4 b0 = *(const float4*)&Bs[k][tc * 8];
            float4 b1 = *(const float4*)&Bs[k][tc * 8 + 4];
            float a[8] = {a0.x, a0.y, a0.z, a0.w, a1.x, a1.y, a1.z, a1.w};
            float bb[8] = {b0.x, b0.y, b0.z, b0.w, b1.x, b1.y, b1.z, b1.w};
#pragma unroll
            for (int i = 0; i < 8; i++)
#pragma unroll
                for (int j = 0; j < 8; j++) acc[i][j] = fmaf(a[i], bb[j], acc[i][j]);
        }
        __syncthreads();
    }
    int part = ntile / DM;       // 0=k, 1=q, 2=v (block entirely within one part)
    int dbase = ntile % DM;
#pragma unroll
    for (int i = 0; i < 8; i++) {
        int m = mtile + tr * 8 + i;
        int b = m / SEQ, si = m % SEQ;
        float mk = mask[b * SEQ + si];
#pragma unroll
        for (int j = 0; j < 8; j++) {
            int n = ntile + tc * 8 + j;
            int d = dbase + tc * 8 + j;
            float val = (acc[i][j] + bias[n]) * mk;
            if (gated && part < 2) val *= g_gate[mod][b][d];   // mod 0->v gate, 1->q gate
            if (part == 0)      g_K[mod][b][rowoff + si][d] = val;
            else if (part == 1) g_Q[mod][b][si][d] = val;
            else                g_V[mod][b][rowoff + si][d] = val;
        }
    }
}

// ---------------- scores: S = mask_fill(Q @ K^T) / sqrt(dh) ----------------
// per (b,h): M=512, N=Sk, K=128. 64x64 tile, BK=16, 256 thr, 4x4 micro.
__global__ void __launch_bounds__(256) score_gemm(
    const float* __restrict__ mask, int mod, int Sk, int hasmem) {
    int bh = blockIdx.z;
    int b = bh / NH, h = bh % NH;
    int sqt = blockIdx.y * 64;
    int skt = blockIdx.x * 64;
    int tid = threadIdx.x;
    int tr = tid >> 4, tc = tid & 15;
    __shared__ __align__(16) float As[16][64];
    __shared__ __align__(16) float Bs[16][64];
    float acc[4][4] = {};
    const float* qbase = &g_Q[mod][b][sqt][h * DH];
    const float* kbase = &g_K[mod][b][0][h * DH];
    for (int k0 = 0; k0 < DH; k0 += 16) {
        {
            int row = tid >> 2;
            int kk = (tid & 3) * 4;
            float4 v = *(const float4*)(qbase + (size_t)row * DM + k0 + kk);
            As[kk + 0][row] = v.x; As[kk + 1][row] = v.y;
            As[kk + 2][row] = v.z; As[kk + 3][row] = v.w;
        }
        {
            int row = tid >> 2;
            int kk = (tid & 3) * 4;
            int sk = skt + row;
            float4 v = make_float4(0.f, 0.f, 0.f, 0.f);
            if (sk < Sk) v = *(const float4*)(kbase + (size_t)sk * DM + k0 + kk);
            Bs[kk + 0][row] = v.x; Bs[kk + 1][row] = v.y;
            Bs[kk + 2][row] = v.z; Bs[kk + 3][row] = v.w;
        }
        __syncthreads();
#pragma unroll
        for (int k = 0; k < 16; k++) {
            float4 av = *(const float4*)&As[k][tr * 4];
            float4 bv = *(const float4*)&Bs[k][tc * 4];
            float a[4] = {av.x, av.y, av.z, av.w};
            float bb[4] = {bv.x, bv.y, bv.z, bv.w};
#pragma unroll
            for (int i = 0; i < 4; i++)
#pragma unroll
                for (int j = 0; j < 4; j++) acc[i][j] = fmaf(a[i], bb[j], acc[i][j]);
        }
        __syncthreads();
    }
    const float scale = 0.08838834764831845f;  // 1/sqrt(128)
#pragma unroll
    for (int i = 0; i < 4; i++) {
#pragma unroll
        for (int j = 0; j < 4; j++) {
            int sq = sqt + tr * 4 + i;
            int sk = skt + tc * 4 + j;
            if (sk >= Sk) continue;
            float km = hasmem ? ((sk == 0) ? 1.f : mask[b * SEQ + sk - 1])
                              : mask[b * SEQ + sk];
            float val = (km != 0.f) ? acc[i][j] : -1e9f;
            g_S[bh][sq][sk] = val * scale;
        }
    }
}

// ---------------- row softmax in place ----------------
__global__ void softmax_kernel(int Sk) {
    int row = blockIdx.x;                 // 0 .. BZ*NH*SEQ-1
    float* p = &g_S[0][0][0] + (size_t)row * SLD;
    __shared__ float red[256];
    int t = threadIdx.x;
    float m = -3.4e38f;
    for (int j = t; j < Sk; j += 256) m = fmaxf(m, p[j]);
    red[t] = m; __syncthreads();
    for (int s = 128; s > 0; s >>= 1) { if (t < s) red[t] = fmaxf(red[t], red[t + s]); __syncthreads(); }
    float M = red[0]; __syncthreads();
    float sum = 0.f;
    for (int j = t; j < Sk; j += 256) { float e = expf(p[j] - M); p[j] = e; sum += e; }
    red[t] = sum; __syncthreads();
    for (int s = 128; s > 0; s >>= 1) { if (t < s) red[t] += red[t + s]; __syncthreads(); }
    float inv = 1.f / red[0];
    for (int j = t; j < Sk; j += 256) p[j] *= inv;
}

// ---------------- AV: U = softmax(S) @ V ----------------
// per (b,h): M=512, N=128, K=Sk. 64x128 tile, BK=16, 256 thr, 4x8 micro.
__global__ void __launch_bounds__(256) av_gemm(int mod, int Sk) {
    int bh = blockIdx.y;
    int b = bh / NH, h = bh % NH;
    int sqt = blockIdx.x * 64;
    int tid = threadIdx.x;
    int tr = tid >> 4, tc = tid & 15;
    __shared__ __align__(16) float Ws[16][64];
    __shared__ __align__(16) float Vs[16][128];
    float acc[4][8] = {};
    const float* wbase = &g_S[bh][sqt][0];
    const float* vbase = &g_V[mod][b][0][h * DH];
    int nk = (Sk + 15) / 16;
    for (int kt = 0; kt < nk; kt++) {
        int k0 = kt * 16;
        {
            int row = tid >> 2;
            int kk = (tid & 3) * 4;
            float4 v;
            if (k0 + kk + 3 < Sk) {
                v = *(const float4*)(wbase + (size_t)row * SLD + k0 + kk);
            } else {
                float tmp[4] = {0.f, 0.f, 0.f, 0.f};
                for (int u = 0; u < 4; u++)
                    if (k0 + kk + u < Sk) tmp[u] = wbase[(size_t)row * SLD + k0 + kk + u];
                v = make_float4(tmp[0], tmp[1], tmp[2], tmp[3]);
            }
            Ws[kk + 0][row] = v.x; Ws[kk + 1][row] = v.y;
            Ws[kk + 2][row] = v.z; Ws[kk + 3][row] = v.w;
        }
#pragma unroll
        for (int l = 0; l < 2; l++) {
            int idx = tid + l * 256;
            int row = idx >> 5;
            int cc = (idx & 31) * 4;
            float4 v = make_float4(0.f, 0.f, 0.f, 0.f);
            if (k0 + row < Sk) v = *(const float4*)(vbase + (size_t)(k0 + row) * DM + cc);
            *(float4*)&Vs[row][cc] = v;
        }
        __syncthreads();
#pragma unroll
        for (int k = 0; k < 16; k++) {
            float4 av = *(const float4*)&Ws[k][tr * 4];
            float4 b0 = *(const float4*)&Vs[k][tc * 8];
            float4 b1 = *(const float4*)&Vs[k][tc * 8 + 4];
            float a[4] = {av.x, av.y, av.z, av.w};
            float bb[8] = {b0.x, b0.y, b0.z, b0.w, b1.x, b1.y, b1.z, b1.w};
#pragma unroll
            for (int i = 0; i < 4; i++)
#pragma unroll
                for (int j = 0; j < 8; j++) acc[i][j] = fmaf(a[i], bb[j], acc[i][j]);
        }
        __syncthreads();
    }
#pragma unroll
    for (int i = 0; i < 4; i++)
#pragma unroll
        for (int j = 0; j < 8; j++)
            g_U[b][sqt + tr * 4 + i][h * DH + tc * 8 + j] = acc[i][j];
}

// ---------------- out projection: out = (X + U) @ W + b ----------------
// M=8192, N=1024, K=1024. 128x128 tile, BK=16.
__global__ void __launch_bounds__(256) outproj_gemm(
    const float* __restrict__ X, const float* __restrict__ W,
    const float* __restrict__ bias, float* __restrict__ out) {
    int mtile = blockIdx.y * 128;
    int ntile = blockIdx.x * 128;
    int tid = threadIdx.x;
    int tr = tid >> 4, tc = tid & 15;
    const float* U = &g_U[0][0][0];
    __shared__ __align__(16) float As[16][128];
    __shared__ __align__(16) float Bs[16][128];
    float acc[8][8] = {};
    for (int k0 = 0; k0 < DM; k0 += 16) {
#pragma unroll
        for (int l = 0; l < 2; l++) {
            int idx = tid + l * 256;
            int row = idx >> 2;
            int kk = (idx & 3) * 4;
            size_t off = (size_t)(mtile + row) * DM + k0 + kk;
            float4 x = *(const float4*)(X + off);
            float4 u = *(const float4*)(U + off);
            As[kk + 0][row] = x.x + u.x;
            As[kk + 1][row] = x.y + u.y;
            As[kk + 2][row] = x.z + u.z;
            As[kk + 3][row] = x.w + u.w;
        }
#pragma unroll
        for (int l = 0; l < 2; l++) {
            int idx = tid + l * 256;
            int row = idx >> 5;
            int cc = (idx & 31) * 4;
            *(float4*)&Bs[row][cc] = *(const float4*)(W + (size_t)(k0 + row) * DM + ntile + cc);
        }
        __syncthreads();
#pragma unroll
        for (int k = 0; k < 16; k++) {
            float4 a0 = *(const float4*)&As[k][tr * 8];
            float4 a1 = *(const float4*)&As[k][tr * 8 + 4];
            float4 b0 = *(const float4*)&Bs[k][tc * 8];
            float4 b1 = *(const float4*)&Bs[k][tc * 8 + 4];
            float a[8] = {a0.x, a0.y, a0.z, a0.w, a1.x, a1.y, a1.z, a1.w};
            float bb[8] = {b0.x, b0.y, b0.z, b0.w, b1.x, b1.y, b1.z, b1.w};
#pragma unroll
            for (int i = 0; i < 8; i++)
#pragma unroll
                for (int j = 0; j < 8; j++) acc[i][j] = fmaf(a[i], bb[j], acc[i][j]);
        }
        __syncthreads();
    }
#pragma unroll
    for (int i = 0; i < 8; i++) {
        int m = mtile + tr * 8 + i;
#pragma unroll
        for (int j = 0; j < 8; j++) {
            int n = ntile + tc * 8 + j;
            out[(size_t)m * DM + n] = acc[i][j] + bias[n];
        }
    }
}

// ---------------- orchestration ----------------
extern "C" void kernel_launch(void* const* d_in, const int* in_sizes, int n_in,
                              void* d_out, int out_size) {
    const float* v      = (const float*)d_in[0];
    const float* q      = (const float*)d_in[1];
    const float* c      = (const float*)d_in[2];
    const float* v_mask = (const float*)d_in[3];
    const float* q_mask = (const float*)d_in[4];
    const float* c_mask = (const float*)d_in[5];
    const float* v4q_w  = (const float*)d_in[6];
    const float* v4q_b  = (const float*)d_in[7];
    const float* q4v_w  = (const float*)d_in[8];
    const float* q4v_b  = (const float*)d_in[9];
    const float* v_lin_w = (const float*)d_in[10];
    const float* v_lin_b = (const float*)d_in[11];
    const float* q_lin_w = (const float*)d_in[12];
    const float* q_lin_b = (const float*)d_in[13];
    const float* c_lin_w = (const float*)d_in[14];
    const float* c_lin_b = (const float*)d_in[15];
    const float* m_v_k  = (const float*)d_in[16];
    const float* m_v_v  = (const float*)d_in[17];
    const float* m_c_k  = (const float*)d_in[18];
    const float* m_c_v  = (const float*)d_in[19];
    const float* v_out_w = (const float*)d_in[20];
    const float* v_out_b = (const float*)d_in[21];
    const float* q_out_w = (const float*)d_in[22];
    const float* q_out_b = (const float*)d_in[23];
    const float* c_out_w = (const float*)d_in[24];
    const float* c_out_b = (const float*)d_in[25];
    float* out = (float*)d_out;

    // 1) masked means
    mean_kernel<<<BZ, 256>>>(v, v_mask, 0);
    mean_kernel<<<BZ, 256>>>(q, q_mask, 1);

    // 2) gates: g_gate[0] = 1+sig(relu(q_mean)@q4v_w+b)  (gates v's q/k)
    //           g_gate[1] = 1+sig(relu(v_mean)@v4q_w+b)  (gates q's q/k)
    gate_kernel<<<dim3(8, BZ), 128>>>(1, q4v_w, q4v_b, 0);
    gate_kernel<<<dim3(8, BZ), 128>>>(0, v4q_w, v4q_b, 1);

    // 3) memory tokens (needs g_gate[0])
    memtok_kernel<<<dim3(8, BZ), 128>>>(m_v_k, m_v_v, m_c_k, m_c_v);

    // 4) trans GEMMs with fused relu/bias/mask/gate/split
    dim3 tg(N3 / 128, (BZ * SEQ) / 128);
    trans_gemm<<<tg, 256>>>(v, v_lin_w, v_lin_b, v_mask, 0, 1, 1);
    trans_gemm<<<tg, 256>>>(q, q_lin_w, q_lin_b, q_mask, 1, 1, 0);
    trans_gemm<<<tg, 256>>>(c, c_lin_w, c_lin_b, c_mask, 2, 0, 1);

    // 5) per-modality attention + out projection (g_S/g_U reused stream-ordered)
    const float* xs[3]    = {v, q, c};
    const float* masks[3] = {v_mask, q_mask, c_mask};
    const float* ows[3]   = {v_out_w, q_out_w, c_out_w};
    const float* obs[3]   = {v_out_b, q_out_b, c_out_b};
    const int    sks[3]   = {SKM, SEQ, SKM};
    const int    hasm[3]  = {1, 0, 1};

    for (int m = 0; m < 3; m++) {
        int Sk = sks[m];
        dim3 sg((Sk + 63) / 64, SEQ / 64, BZ * NH);
        score_gemm<<<sg, 256>>>(masks[m], m, Sk, hasm[m]);
        softmax_kernel<<<BZ * NH * SEQ, 256>>>(Sk);
        av_gemm<<<dim3(SEQ / 64, BZ * NH), 256>>>(m, Sk);
        outproj_gemm<<<dim3(DM / 128, (BZ * SEQ) / 128), 256>>>(
            xs[m], ows[m], obs[m], out + (size_t)m * BZ * SEQ * DM);
    }
}

// round 7
// speedup vs baseline: 1.6378x; 1.6378x over previous
#include <cuda_runtime.h>
#include <math.h>
#include <stdint.h>

#define BZ   16
#define SEQ  512
#define DM   1024
#define NH   8
#define DH   128
#define SKM  513          // keys with memory token
#define SLD  516          // scores leading dim (mult of 4 for float4)
#define N3   3072

// ---------------- static scratch (device globals; allocation-free) ----------
__device__ float g_mean[2][BZ][DM];
__device__ float g_gate[2][BZ][DM];
__device__ float g_K[3][BZ][SEQ + 1][DM];
__device__ float g_Q[3][BZ][SEQ][DM];
__device__ float g_V[3][BZ][SEQ + 1][DM];
__device__ float g_S[BZ * NH][SEQ][SLD];
__device__ float g_U[BZ][SEQ][DM];

__device__ __forceinline__ uint32_t f2tf32(float x) {
    uint32_t r; asm("cvt.rna.tf32.f32 %0, %1;" : "=r"(r) : "f"(x)); return r;
}

// ============ tf32 mma.sync GEMM: 128x128x32 tile, 256 thr, 8 warps ========
// warp grid 2(m) x 4(n); warp tile 64x32; m16n8k8 fragments.
// mode 0: D = (relu(A) @ W + bias) * mask, optional gate, scatter to g_K/Q/V
// mode 1: D = ((A + g_U) @ W + bias) -> outp
__global__ void __launch_bounds__(256) gemm_mma(
    const float* __restrict__ A, const float* __restrict__ W,
    const float* __restrict__ bias, const float* __restrict__ mask,
    float* __restrict__ outp,
    int Ntot, int mode, int mod, int gated, int rowoff) {
    __shared__ float As[128][36];   // row-major [m][k], pad 36
    __shared__ float Bs[32][132];   // row-major [k][n], pad 132

    int tid = threadIdx.x;
    int wid = tid >> 5, lane = tid & 31;
    int g = lane >> 2, u = lane & 3;
    int wm = (wid >> 2) * 64;       // warp m offset in tile
    int wn = (wid & 3) * 32;        // warp n offset in tile
    int mtile = blockIdx.y * 128;
    int ntile = blockIdx.x * 128;

    float acc[4][4][4];
#pragma unroll
    for (int i = 0; i < 4; i++)
#pragma unroll
        for (int j = 0; j < 4; j++)
#pragma unroll
            for (int e = 0; e < 4; e++) acc[i][j][e] = 0.f;

    const float* Uf = &g_U[0][0][0];

    for (int kt = 0; kt < 32; kt++) {
        int k0 = kt * 32;
        // ---- A tile: 128x32, relu or +U, fp32 into padded smem ----
#pragma unroll
        for (int l = 0; l < 4; l++) {
            int idx = tid + l * 256;
            int row = idx >> 3;
            int c4 = (idx & 7) * 4;
            size_t off = (size_t)(mtile + row) * DM + k0 + c4;
            float4 v = *(const float4*)(A + off);
            if (mode == 0) {
                v.x = fmaxf(v.x, 0.f); v.y = fmaxf(v.y, 0.f);
                v.z = fmaxf(v.z, 0.f); v.w = fmaxf(v.w, 0.f);
            } else {
                float4 uu = *(const float4*)(Uf + off);
                v.x += uu.x; v.y += uu.y; v.z += uu.z; v.w += uu.w;
            }
            *(float4*)&As[row][c4] = v;
        }
        // ---- B tile: 32x128 from W[k][n] (already k-major rows) ----
#pragma unroll
        for (int l = 0; l < 4; l++) {
            int idx = tid + l * 256;
            int kr = idx >> 5;
            int nc = (idx & 31) * 4;
            *(float4*)&Bs[kr][nc] = *(const float4*)(W + (size_t)(k0 + kr) * Ntot + ntile + nc);
        }
        __syncthreads();

#pragma unroll
        for (int ks = 0; ks < 4; ks++) {
            int kk = ks * 8;
            uint32_t af[4][4], bf[4][2];
#pragma unroll
            for (int i = 0; i < 4; i++) {
                int m = wm + i * 16 + g;
                af[i][0] = f2tf32(As[m][kk + u]);
                af[i][1] = f2tf32(As[m + 8][kk + u]);
                af[i][2] = f2tf32(As[m][kk + u + 4]);
                af[i][3] = f2tf32(As[m + 8][kk + u + 4]);
            }
#pragma unroll
            for (int j = 0; j < 4; j++) {
                int n = wn + j * 8 + g;
                bf[j][0] = f2tf32(Bs[kk + u][n]);
                bf[j][1] = f2tf32(Bs[kk + u + 4][n]);
            }
#pragma unroll
            for (int i = 0; i < 4; i++)
#pragma unroll
                for (int j = 0; j < 4; j++)
                    asm volatile(
                        "mma.sync.aligned.m16n8k8.row.col.f32.tf32.tf32.f32 "
                        "{%0,%1,%2,%3}, {%4,%5,%6,%7}, {%8,%9}, {%0,%1,%2,%3};"
                        : "+f"(acc[i][j][0]), "+f"(acc[i][j][1]),
                          "+f"(acc[i][j][2]), "+f"(acc[i][j][3])
                        : "r"(af[i][0]), "r"(af[i][1]), "r"(af[i][2]), "r"(af[i][3]),
                          "r"(bf[j][0]), "r"(bf[j][1]));
        }
        __syncthreads();
    }

    // ---- epilogue ----
    // fragment element mapping: rows r0 = base+g, r1 = r0+8; cols col, col+1
    int part = ntile >> 10;               // whole block lives in one k/q/v part
#pragma unroll
    for (int i = 0; i < 4; i++) {
        int r0 = mtile + wm + i * 16 + g;
        int r1 = r0 + 8;
#pragma unroll
        for (int j = 0; j < 4; j++) {
            int col = ntile + wn + j * 8 + u * 2;    // global n
            if (mode == 1) {
                float b0 = bias[col], b1 = bias[col + 1];
                *(float2*)(outp + (size_t)r0 * DM + col) =
                    make_float2(acc[i][j][0] + b0, acc[i][j][1] + b1);
                *(float2*)(outp + (size_t)r1 * DM + col) =
                    make_float2(acc[i][j][2] + b0, acc[i][j][3] + b1);
            } else {
                float b0 = bias[col], b1 = bias[col + 1];
                int d0 = col & 1023;
#pragma unroll
                for (int h = 0; h < 2; h++) {
                    int r = h ? r1 : r0;
                    int b = r >> 9, si = r & 511;
                    float mk = mask[r];
                    float v0 = (acc[i][j][h * 2 + 0] + b0) * mk;
                    float v1 = (acc[i][j][h * 2 + 1] + b1) * mk;
                    if (gated && part < 2) {
                        v0 *= g_gate[mod][b][d0];
                        v1 *= g_gate[mod][b][d0 + 1];
                    }
                    float* dst;
                    if (part == 0)      dst = &g_K[mod][b][rowoff + si][d0];
                    else if (part == 1) dst = &g_Q[mod][b][si][d0];
                    else                dst = &g_V[mod][b][rowoff + si][d0];
                    *(float2*)dst = make_float2(v0, v1);
                }
            }
        }
    }
}

// ---------------- masked mean ----------------
__global__ void mean_kernel(const float* __restrict__ x, const float* __restrict__ mask, int slot) {
    int b = blockIdx.x;
    __shared__ float sm[SEQ];
    __shared__ float smsum;
    for (int i = threadIdx.x; i < SEQ; i += blockDim.x) sm[i] = mask[b * SEQ + i];
    __syncthreads();
    if (threadIdx.x == 0) {
        float s = 0.f;
        for (int i = 0; i < SEQ; i++) s += sm[i];
        smsum = s;
    }
    __syncthreads();
    float inv = 1.f / smsum;
    for (int d = threadIdx.x; d < DM; d += blockDim.x) {
        float acc = 0.f;
        for (int i = 0; i < SEQ; i++) acc += x[(b * SEQ + i) * DM + d] * sm[i];
        g_mean[slot][b][d] = acc * inv;
    }
}

// ---------------- gate = 1 + sigmoid(relu(mean) @ w + b) ----------------
__global__ void gate_kernel(int mean_slot, const float* __restrict__ w,
                            const float* __restrict__ bias, int gate_slot) {
    int b = blockIdx.y;
    int d = blockIdx.x * 128 + threadIdx.x;
    __shared__ float sm[DM];
    for (int k = threadIdx.x; k < DM; k += 128) sm[k] = fmaxf(g_mean[mean_slot][b][k], 0.f);
    __syncthreads();
    float acc = bias[d];
    for (int k = 0; k < DM; k++) acc = fmaf(sm[k], w[k * DM + d], acc);
    g_gate[gate_slot][b][d] = 1.f + 1.f / (1.f + expf(-acc));
}

// ---------------- memory tokens ----------------
__global__ void memtok_kernel(const float* __restrict__ mvk, const float* __restrict__ mvv,
                              const float* __restrict__ mck, const float* __restrict__ mcv) {
    int b = blockIdx.y;
    int d = blockIdx.x * 128 + threadIdx.x;
    float gv = g_gate[0][b][d];
    g_K[0][b][0][d] = 32.f * mvk[d] * gv;
    g_V[0][b][0][d] = mvv[d];
    g_K[2][b][0][d] = 32.f * mck[d];
    g_V[2][b][0][d] = mcv[d];
}

// ---------------- scores: S = mask_fill(Q @ K^T) / sqrt(dh) ----------------
__global__ void __launch_bounds__(256) score_gemm(
    const float* __restrict__ mask, int mod, int Sk, int hasmem) {
    int bh = blockIdx.z;
    int b = bh / NH, h = bh % NH;
    int sqt = blockIdx.y * 64;
    int skt = blockIdx.x * 64;
    int tid = threadIdx.x;
    int tr = tid >> 4, tc = tid & 15;
    __shared__ __align__(16) float As[16][64];
    __shared__ __align__(16) float Bs[16][64];
    float acc[4][4] = {};
    const float* qbase = &g_Q[mod][b][sqt][h * DH];
    const float* kbase = &g_K[mod][b][0][h * DH];
    for (int k0 = 0; k0 < DH; k0 += 16) {
        {
            int row = tid >> 2;
            int kk = (tid & 3) * 4;
            float4 v = *(const float4*)(qbase + (size_t)row * DM + k0 + kk);
            As[kk + 0][row] = v.x; As[kk + 1][row] = v.y;
            As[kk + 2][row] = v.z; As[kk + 3][row] = v.w;
        }
        {
            int row = tid >> 2;
            int kk = (tid & 3) * 4;
            int sk = skt + row;
            float4 v = make_float4(0.f, 0.f, 0.f, 0.f);
            if (sk < Sk) v = *(const float4*)(kbase + (size_t)sk * DM + k0 + kk);
            Bs[kk + 0][row] = v.x; Bs[kk + 1][row] = v.y;
            Bs[kk + 2][row] = v.z; Bs[kk + 3][row] = v.w;
        }
        __syncthreads();
#pragma unroll
        for (int k = 0; k < 16; k++) {
            float4 av = *(const float4*)&As[k][tr * 4];
            float4 bv = *(const float4*)&Bs[k][tc * 4];
            float a[4] = {av.x, av.y, av.z, av.w};
            float bb[4] = {bv.x, bv.y, bv.z, bv.w};
#pragma unroll
            for (int i = 0; i < 4; i++)
#pragma unroll
                for (int j = 0; j < 4; j++) acc[i][j] = fmaf(a[i], bb[j], acc[i][j]);
        }
        __syncthreads();
    }
    const float scale = 0.08838834764831845f;
#pragma unroll
    for (int i = 0; i < 4; i++) {
#pragma unroll
        for (int j = 0; j < 4; j++) {
            int sq = sqt + tr * 4 + i;
            int sk = skt + tc * 4 + j;
            if (sk >= Sk) continue;
            float km = hasmem ? ((sk == 0) ? 1.f : mask[b * SEQ + sk - 1])
                              : mask[b * SEQ + sk];
            float val = (km != 0.f) ? acc[i][j] : -1e9f;
            g_S[bh][sq][sk] = val * scale;
        }
    }
}

// ---------------- row softmax in place ----------------
__global__ void softmax_kernel(int Sk) {
    int row = blockIdx.x;
    float* p = &g_S[0][0][0] + (size_t)row * SLD;
    __shared__ float red[256];
    int t = threadIdx.x;
    float m = -3.4e38f;
    for (int j = t; j < Sk; j += 256) m = fmaxf(m, p[j]);
    red[t] = m; __syncthreads();
    for (int s = 128; s > 0; s >>= 1) { if (t < s) red[t] = fmaxf(red[t], red[t + s]); __syncthreads(); }
    float M = red[0]; __syncthreads();
    float sum = 0.f;
    for (int j = t; j < Sk; j += 256) { float e = expf(p[j] - M); p[j] = e; sum += e; }
    red[t] = sum; __syncthreads();
    for (int s = 128; s > 0; s >>= 1) { if (t < s) red[t] += red[t + s]; __syncthreads(); }
    float inv = 1.f / red[0];
    for (int j = t; j < Sk; j += 256) p[j] *= inv;
}

// ---------------- AV: U = softmax(S) @ V ----------------
__global__ void __launch_bounds__(256) av_gemm(int mod, int Sk) {
    int bh = blockIdx.y;
    int b = bh / NH, h = bh % NH;
    int sqt = blockIdx.x * 64;
    int tid = threadIdx.x;
    int tr = tid >> 4, tc = tid & 15;
    __shared__ __align__(16) float Ws[16][64];
    __shared__ __align__(16) float Vs[16][128];
    float acc[4][8] = {};
    const float* wbase = &g_S[bh][sqt][0];
    const float* vbase = &g_V[mod][b][0][h * DH];
    int nk = (Sk + 15) / 16;
    for (int kt = 0; kt < nk; kt++) {
        int k0 = kt * 16;
        {
            int row = tid >> 2;
            int kk = (tid & 3) * 4;
            float4 v;
            if (k0 + kk + 3 < Sk) {
                v = *(const float4*)(wbase + (size_t)row * SLD + k0 + kk);
            } else {
                float tmp[4] = {0.f, 0.f, 0.f, 0.f};
                for (int uu = 0; uu < 4; uu++)
                    if (k0 + kk + uu < Sk) tmp[uu] = wbase[(size_t)row * SLD + k0 + kk + uu];
                v = make_float4(tmp[0], tmp[1], tmp[2], tmp[3]);
            }
            Ws[kk + 0][row] = v.x; Ws[kk + 1][row] = v.y;
            Ws[kk + 2][row] = v.z; Ws[kk + 3][row] = v.w;
        }
#pragma unroll
        for (int l = 0; l < 2; l++) {
            int idx = tid + l * 256;
            int row = idx >> 5;
            int cc = (idx & 31) * 4;
            float4 v = make_float4(0.f, 0.f, 0.f, 0.f);
            if (k0 + row < Sk) v = *(const float4*)(vbase + (size_t)(k0 + row) * DM + cc);
            *(float4*)&Vs[row][cc] = v;
        }
        __syncthreads();
#pragma unroll
        for (int k = 0; k < 16; k++) {
            float4 av = *(const float4*)&Ws[k][tr * 4];
            float4 b0 = *(const float4*)&Vs[k][tc * 8];
            float4 b1 = *(const float4*)&Vs[k][tc * 8 + 4];
            float a[4] = {av.x, av.y, av.z, av.w};
            float bb[8] = {b0.x, b0.y, b0.z, b0.w, b1.x, b1.y, b1.z, b1.w};
#pragma unroll
            for (int i = 0; i < 4; i++)
#pragma unroll
                for (int j = 0; j < 8; j++) acc[i][j] = fmaf(a[i], bb[j], acc[i][j]);
        }
        __syncthreads();
    }
#pragma unroll
    for (int i = 0; i < 4; i++)
#pragma unroll
        for (int j = 0; j < 8; j++)
            g_U[b][sqt + tr * 4 + i][h * DH + tc * 8 + j] = acc[i][j];
}

// ---------------- orchestration ----------------
extern "C" void kernel_launch(void* const* d_in, const int* in_sizes, int n_in,
                              void* d_out, int out_size) {
    const float* v      = (const float*)d_in[0];
    const float* q      = (const float*)d_in[1];
    const float* c      = (const float*)d_in[2];
    const float* v_mask = (const float*)d_in[3];
    const float* q_mask = (const float*)d_in[4];
    const float* c_mask = (const float*)d_in[5];
    const float* v4q_w  = (const float*)d_in[6];
    const float* v4q_b  = (const float*)d_in[7];
    const float* q4v_w  = (const float*)d_in[8];
    const float* q4v_b  = (const float*)d_in[9];
    const float* v_lin_w = (const float*)d_in[10];
    const float* v_lin_b = (const float*)d_in[11];
    const float* q_lin_w = (const float*)d_in[12];
    const float* q_lin_b = (const float*)d_in[13];
    const float* c_lin_w = (const float*)d_in[14];
    const float* c_lin_b = (const float*)d_in[15];
    const float* m_v_k  = (const float*)d_in[16];
    const float* m_v_v  = (const float*)d_in[17];
    const float* m_c_k  = (const float*)d_in[18];
    const float* m_c_v  = (const float*)d_in[19];
    const float* v_out_w = (const float*)d_in[20];
    const float* v_out_b = (const float*)d_in[21];
    const float* q_out_w = (const float*)d_in[22];
    const float* q_out_b = (const float*)d_in[23];
    const float* c_out_w = (const float*)d_in[24];
    const float* c_out_b = (const float*)d_in[25];
    float* out = (float*)d_out;

    // 1) masked means
    mean_kernel<<<BZ, 256>>>(v, v_mask, 0);
    mean_kernel<<<BZ, 256>>>(q, q_mask, 1);

    // 2) gates
    gate_kernel<<<dim3(8, BZ), 128>>>(1, q4v_w, q4v_b, 0);
    gate_kernel<<<dim3(8, BZ), 128>>>(0, v4q_w, v4q_b, 1);

    // 3) memory tokens
    memtok_kernel<<<dim3(8, BZ), 128>>>(m_v_k, m_v_v, m_c_k, m_c_v);

    // 4) trans GEMMs via tf32 mma.sync
    dim3 tg(N3 / 128, (BZ * SEQ) / 128);
    gemm_mma<<<tg, 256>>>(v, v_lin_w, v_lin_b, v_mask, nullptr, N3, 0, 0, 1, 1);
    gemm_mma<<<tg, 256>>>(q, q_lin_w, q_lin_b, q_mask, nullptr, N3, 0, 1, 1, 0);
    gemm_mma<<<tg, 256>>>(c, c_lin_w, c_lin_b, c_mask, nullptr, N3, 0, 2, 0, 1);

    // 5) per-modality attention + out projection
    const float* xs[3]    = {v, q, c};
    const float* masks[3] = {v_mask, q_mask, c_mask};
    const float* ows[3]   = {v_out_w, q_out_w, c_out_w};
    const float* obs[3]   = {v_out_b, q_out_b, c_out_b};
    const int    sks[3]   = {SKM, SEQ, SKM};
    const int    hasm[3]  = {1, 0, 1};

    dim3 og(DM / 128, (BZ * SEQ) / 128);
    for (int m = 0; m < 3; m++) {
        int Sk = sks[m];
        dim3 sg((Sk + 63) / 64, SEQ / 64, BZ * NH);
        score_gemm<<<sg, 256>>>(masks[m], m, Sk, hasm[m]);
        softmax_kernel<<<BZ * NH * SEQ, 256>>>(Sk);
        av_gemm<<<dim3(SEQ / 64, BZ * NH), 256>>>(m, Sk);
        gemm_mma<<<og, 256>>>(xs[m], ows[m], obs[m], nullptr,
                              out + (size_t)m * BZ * SEQ * DM,
                              DM, 1, 0, 0, 0);
    }
}

// round 8
// speedup vs baseline: 2.5323x; 1.5461x over previous
#include <cuda_runtime.h>
#include <math.h>
#include <stdint.h>

#define BZ   16
#define SEQ  512
#define DM   1024
#define NH   8
#define DH   128
#define SKM  513          // keys with memory token
#define N3   3072

// ---------------- static scratch (device globals; allocation-free) ----------
__device__ float g_mean[2][BZ][DM];
__device__ float g_gate[2][BZ][DM];
__device__ float g_K[3][BZ][SEQ + 1][DM];
__device__ float g_Q[3][BZ][SEQ][DM];
__device__ float g_V[3][BZ][SEQ + 1][DM];
__device__ float g_U[BZ][SEQ][DM];

__device__ __forceinline__ uint32_t f2tf32(float x) {
    uint32_t r; asm("cvt.rna.tf32.f32 %0, %1;" : "=r"(r) : "f"(x)); return r;
}
__device__ __forceinline__ void mma_tf32(float* c, uint32_t a0, uint32_t a1,
                                         uint32_t a2, uint32_t a3,
                                         uint32_t b0, uint32_t b1) {
    asm volatile(
        "mma.sync.aligned.m16n8k8.row.col.f32.tf32.tf32.f32 "
        "{%0,%1,%2,%3}, {%4,%5,%6,%7}, {%8,%9}, {%0,%1,%2,%3};"
        : "+f"(c[0]), "+f"(c[1]), "+f"(c[2]), "+f"(c[3])
        : "r"(a0), "r"(a1), "r"(a2), "r"(a3), "r"(b0), "r"(b1));
}

// ============ tf32 mma.sync GEMM: 128x128x32 tile, 256 thr, 8 warps ========
__global__ void __launch_bounds__(256) gemm_mma(
    const float* __restrict__ A, const float* __restrict__ W,
    const float* __restrict__ bias, const float* __restrict__ mask,
    float* __restrict__ outp,
    int Ntot, int mode, int mod, int gated, int rowoff) {
    __shared__ float As[128][36];
    __shared__ float Bs[32][132];

    int tid = threadIdx.x;
    int wid = tid >> 5, lane = tid & 31;
    int g = lane >> 2, u = lane & 3;
    int wm = (wid >> 2) * 64;
    int wn = (wid & 3) * 32;
    int mtile = blockIdx.y * 128;
    int ntile = blockIdx.x * 128;

    float acc[4][4][4];
#pragma unroll
    for (int i = 0; i < 4; i++)
#pragma unroll
        for (int j = 0; j < 4; j++)
#pragma unroll
            for (int e = 0; e < 4; e++) acc[i][j][e] = 0.f;

    const float* Uf = &g_U[0][0][0];

    for (int kt = 0; kt < 32; kt++) {
        int k0 = kt * 32;
#pragma unroll
        for (int l = 0; l < 4; l++) {
            int idx = tid + l * 256;
            int row = idx >> 3;
            int c4 = (idx & 7) * 4;
            size_t off = (size_t)(mtile + row) * DM + k0 + c4;
            float4 v = *(const float4*)(A + off);
            if (mode == 0) {
                v.x = fmaxf(v.x, 0.f); v.y = fmaxf(v.y, 0.f);
                v.z = fmaxf(v.z, 0.f); v.w = fmaxf(v.w, 0.f);
            } else {
                float4 uu = *(const float4*)(Uf + off);
                v.x += uu.x; v.y += uu.y; v.z += uu.z; v.w += uu.w;
            }
            *(float4*)&As[row][c4] = v;
        }
#pragma unroll
        for (int l = 0; l < 4; l++) {
            int idx = tid + l * 256;
            int kr = idx >> 5;
            int nc = (idx & 31) * 4;
            *(float4*)&Bs[kr][nc] = *(const float4*)(W + (size_t)(k0 + kr) * Ntot + ntile + nc);
        }
        __syncthreads();

#pragma unroll
        for (int ks = 0; ks < 4; ks++) {
            int kk = ks * 8;
            uint32_t af[4][4], bf[4][2];
#pragma unroll
            for (int i = 0; i < 4; i++) {
                int m = wm + i * 16 + g;
                af[i][0] = f2tf32(As[m][kk + u]);
                af[i][1] = f2tf32(As[m + 8][kk + u]);
                af[i][2] = f2tf32(As[m][kk + u + 4]);
                af[i][3] = f2tf32(As[m + 8][kk + u + 4]);
            }
#pragma unroll
            for (int j = 0; j < 4; j++) {
                int n = wn + j * 8 + g;
                bf[j][0] = f2tf32(Bs[kk + u][n]);
                bf[j][1] = f2tf32(Bs[kk + u + 4][n]);
            }
#pragma unroll
            for (int i = 0; i < 4; i++)
#pragma unroll
                for (int j = 0; j < 4; j++)
                    mma_tf32(acc[i][j], af[i][0], af[i][1], af[i][2], af[i][3],
                             bf[j][0], bf[j][1]);
        }
        __syncthreads();
    }

    int part = ntile >> 10;
#pragma unroll
    for (int i = 0; i < 4; i++) {
        int r0 = mtile + wm + i * 16 + g;
        int r1 = r0 + 8;
#pragma unroll
        for (int j = 0; j < 4; j++) {
            int col = ntile + wn + j * 8 + u * 2;
            if (mode == 1) {
                float b0 = bias[col], b1 = bias[col + 1];
                *(float2*)(outp + (size_t)r0 * DM + col) =
                    make_float2(acc[i][j][0] + b0, acc[i][j][1] + b1);
                *(float2*)(outp + (size_t)r1 * DM + col) =
                    make_float2(acc[i][j][2] + b0, acc[i][j][3] + b1);
            } else {
                float b0 = bias[col], b1 = bias[col + 1];
                int d0 = col & 1023;
#pragma unroll
                for (int h = 0; h < 2; h++) {
                    int r = h ? r1 : r0;
                    int b = r >> 9, si = r & 511;
                    float mk = mask[r];
                    float v0 = (acc[i][j][h * 2 + 0] + b0) * mk;
                    float v1 = (acc[i][j][h * 2 + 1] + b1) * mk;
                    if (gated && part < 2) {
                        v0 *= g_gate[mod][b][d0];
                        v1 *= g_gate[mod][b][d0 + 1];
                    }
                    float* dst;
                    if (part == 0)      dst = &g_K[mod][b][rowoff + si][d0];
                    else if (part == 1) dst = &g_Q[mod][b][si][d0];
                    else                dst = &g_V[mod][b][rowoff + si][d0];
                    *(float2*)dst = make_float2(v0, v1);
                }
            }
        }
    }
}

// ================= fused flash attention (tf32 mma) =========================
// block = (q-tile of 64 rows, bh). 8 warps: 4(m) x 2(n).
// smem: Qs/Ks/Vs [64][132] tf32 bits, Ps [64][68] tf32 bits, softmax state.
#define FA_LDQ 132
#define FA_LDP 68
#define FA_SMEM (3 * 64 * FA_LDQ * 4 + 64 * FA_LDP * 4 + (64 * 6 + 128) * 4)

__global__ void __launch_bounds__(256) flash_attn(
    const float* __restrict__ mask, int mod, int Sk, int hasmem) {
    extern __shared__ char smraw[];
    uint32_t* Qs = (uint32_t*)smraw;
    uint32_t* Ks = Qs + 64 * FA_LDQ;
    uint32_t* Vs = Ks + 64 * FA_LDQ;
    uint32_t* Ps = Vs + 64 * FA_LDQ;
    float* m_s  = (float*)(Ps + 64 * FA_LDP);
    float* l_s  = m_s + 64;
    float* al_s = l_s + 64;
    float* red  = al_s + 64;     // [2][64]
    float* kms  = red + 128;

    int tid = threadIdx.x;
    int wid = tid >> 5, lane = tid & 31;
    int g = lane >> 2, u = lane & 3;
    int wm = (wid >> 1) * 16;
    int wns = (wid & 1) * 32;
    int wno = (wid & 1) * 64;
    int bh = blockIdx.y;
    int b = bh >> 3, h = bh & 7;
    int qt0 = blockIdx.x * 64;

    const float* Qg = &g_Q[mod][b][0][h * DH];
    const float* Kg = &g_K[mod][b][0][h * DH];
    const float* Vg = &g_V[mod][b][0][h * DH];

    // load Q tile once (tf32 bits)
#pragma unroll
    for (int l = 0; l < 8; l++) {
        int idx = tid + l * 256;
        int row = idx >> 5;
        int c4 = (idx & 31) * 4;
        float4 v = *(const float4*)(Qg + (size_t)(qt0 + row) * DM + c4);
        uint32_t* d = &Qs[row * FA_LDQ + c4];
        d[0] = f2tf32(v.x); d[1] = f2tf32(v.y); d[2] = f2tf32(v.z); d[3] = f2tf32(v.w);
    }
    if (tid < 64) { m_s[tid] = -3.4e38f; l_s[tid] = 0.f; }

    float acc_o[8][4];
#pragma unroll
    for (int j = 0; j < 8; j++)
#pragma unroll
        for (int e = 0; e < 4; e++) acc_o[j][e] = 0.f;

    const float scl = 0.08838834764831845f;   // 1/sqrt(128)
    int r0l = wm + g, r1l = wm + g + 8;       // local rows
    int nt = (Sk + 63) >> 6;

    for (int t = 0; t < nt; t++) {
        int kt0 = t * 64;
        __syncthreads();   // A: protect Ks/Vs vs prev PV reads
        // load K,V tiles (guarded)
#pragma unroll
        for (int l = 0; l < 8; l++) {
            int idx = tid + l * 256;
            int row = idx >> 5;
            int c4 = (idx & 31) * 4;
            int key = kt0 + row;
            float4 kv = make_float4(0.f, 0.f, 0.f, 0.f);
            float4 vv = make_float4(0.f, 0.f, 0.f, 0.f);
            if (key < Sk) {
                kv = *(const float4*)(Kg + (size_t)key * DM + c4);
                vv = *(const float4*)(Vg + (size_t)key * DM + c4);
            }
            uint32_t* dk = &Ks[row * FA_LDQ + c4];
            dk[0] = f2tf32(kv.x); dk[1] = f2tf32(kv.y); dk[2] = f2tf32(kv.z); dk[3] = f2tf32(kv.w);
            uint32_t* dv = &Vs[row * FA_LDQ + c4];
            dv[0] = f2tf32(vv.x); dv[1] = f2tf32(vv.y); dv[2] = f2tf32(vv.z); dv[3] = f2tf32(vv.w);
        }
        if (tid < 64) {
            int key = kt0 + tid;
            float km = 0.f;
            if (key < Sk)
                km = hasmem ? ((key == 0) ? 1.f : mask[b * SEQ + key - 1])
                            : mask[b * SEQ + key];
            kms[tid] = km;
        }
        __syncthreads();   // B

        // ---- S = Q @ K^T (64x64) ----
        float s[4][4];
#pragma unroll
        for (int j = 0; j < 4; j++)
#pragma unroll
            for (int e = 0; e < 4; e++) s[j][e] = 0.f;
#pragma unroll
        for (int kk = 0; kk < 16; kk++) {
            int k8 = kk * 8;
            uint32_t a0 = Qs[r0l * FA_LDQ + k8 + u];
            uint32_t a1 = Qs[r1l * FA_LDQ + k8 + u];
            uint32_t a2 = Qs[r0l * FA_LDQ + k8 + u + 4];
            uint32_t a3 = Qs[r1l * FA_LDQ + k8 + u + 4];
#pragma unroll
            for (int j = 0; j < 4; j++) {
                int n = wns + j * 8 + g;
                uint32_t b0 = Ks[n * FA_LDQ + k8 + u];
                uint32_t b1 = Ks[n * FA_LDQ + k8 + u + 4];
                mma_tf32(s[j], a0, a1, a2, a3, b0, b1);
            }
        }
        // ---- mask + scale ----
        float rm0 = -3.4e38f, rm1 = -3.4e38f;
#pragma unroll
        for (int j = 0; j < 4; j++) {
            int col = wns + j * 8 + u * 2;
            float k0m = kms[col], k1m = kms[col + 1];
            s[j][0] = (k0m != 0.f ? s[j][0] : -1e9f) * scl;
            s[j][1] = (k1m != 0.f ? s[j][1] : -1e9f) * scl;
            s[j][2] = (k0m != 0.f ? s[j][2] : -1e9f) * scl;
            s[j][3] = (k1m != 0.f ? s[j][3] : -1e9f) * scl;
            rm0 = fmaxf(rm0, fmaxf(s[j][0], s[j][1]));
            rm1 = fmaxf(rm1, fmaxf(s[j][2], s[j][3]));
        }
        rm0 = fmaxf(rm0, __shfl_xor_sync(0xffffffffu, rm0, 1));
        rm0 = fmaxf(rm0, __shfl_xor_sync(0xffffffffu, rm0, 2));
        rm1 = fmaxf(rm1, __shfl_xor_sync(0xffffffffu, rm1, 1));
        rm1 = fmaxf(rm1, __shfl_xor_sync(0xffffffffu, rm1, 2));
        if (u == 0) {
            red[(wid & 1) * 64 + r0l] = rm0;
            red[(wid & 1) * 64 + r1l] = rm1;
        }
        __syncthreads();   // C
        if ((wid & 1) == 0 && u == 0) {
#pragma unroll
            for (int hh = 0; hh < 2; hh++) {
                int r = hh ? r1l : r0l;
                float tm = fmaxf(red[r], red[64 + r]);
                float mo = m_s[r];
                float mn = fmaxf(mo, tm);
                al_s[r] = expf(mo - mn);
                m_s[r] = mn;
            }
        }
        __syncthreads();   // D
        float mn0 = m_s[r0l], mn1 = m_s[r1l];
        float rs0 = 0.f, rs1 = 0.f;
#pragma unroll
        for (int j = 0; j < 4; j++) {
            int col = wns + j * 8 + u * 2;
            float p0 = expf(s[j][0] - mn0);
            float p1 = expf(s[j][1] - mn0);
            float p2 = expf(s[j][2] - mn1);
            float p3 = expf(s[j][3] - mn1);
            rs0 += p0 + p1; rs1 += p2 + p3;
            Ps[r0l * FA_LDP + col]     = f2tf32(p0);
            Ps[r0l * FA_LDP + col + 1] = f2tf32(p1);
            Ps[r1l * FA_LDP + col]     = f2tf32(p2);
            Ps[r1l * FA_LDP + col + 1] = f2tf32(p3);
        }
        rs0 += __shfl_xor_sync(0xffffffffu, rs0, 1);
        rs0 += __shfl_xor_sync(0xffffffffu, rs0, 2);
        rs1 += __shfl_xor_sync(0xffffffffu, rs1, 1);
        rs1 += __shfl_xor_sync(0xffffffffu, rs1, 2);
        if (u == 0) {
            red[(wid & 1) * 64 + r0l] = rs0;
            red[(wid & 1) * 64 + r1l] = rs1;
        }
        __syncthreads();   // E: Ps + sums visible
        if ((wid & 1) == 0 && u == 0) {
            l_s[r0l] = l_s[r0l] * al_s[r0l] + red[r0l] + red[64 + r0l];
            l_s[r1l] = l_s[r1l] * al_s[r1l] + red[r1l] + red[64 + r1l];
        }
        // rescale O, then O += P @ V
        float a0s = al_s[r0l], a1s = al_s[r1l];
#pragma unroll
        for (int j = 0; j < 8; j++) {
            acc_o[j][0] *= a0s; acc_o[j][1] *= a0s;
            acc_o[j][2] *= a1s; acc_o[j][3] *= a1s;
        }
#pragma unroll
        for (int ks = 0; ks < 8; ks++) {
            int k8 = ks * 8;
            uint32_t a0 = Ps[r0l * FA_LDP + k8 + u];
            uint32_t a1 = Ps[r1l * FA_LDP + k8 + u];
            uint32_t a2 = Ps[r0l * FA_LDP + k8 + u + 4];
            uint32_t a3 = Ps[r1l * FA_LDP + k8 + u + 4];
#pragma unroll
            for (int j = 0; j < 8; j++) {
                int n = wno + j * 8 + g;
                uint32_t b0 = Vs[(k8 + u) * FA_LDQ + n];
                uint32_t b1 = Vs[(k8 + u + 4) * FA_LDQ + n];
                mma_tf32(acc_o[j], a0, a1, a2, a3, b0, b1);
            }
        }
    }
    __syncthreads();   // final l_s visible
    float inv0 = 1.f / l_s[r0l];
    float inv1 = 1.f / l_s[r1l];
    int qr0 = qt0 + r0l, qr1 = qt0 + r1l;
#pragma unroll
    for (int j = 0; j < 8; j++) {
        int col = h * DH + wno + j * 8 + u * 2;
        *(float2*)&g_U[b][qr0][col] =
            make_float2(acc_o[j][0] * inv0, acc_o[j][1] * inv0);
        *(float2*)&g_U[b][qr1][col] =
            make_float2(acc_o[j][2] * inv1, acc_o[j][3] * inv1);
    }
}

// ---------------- masked mean ----------------
__global__ void mean_kernel(const float* __restrict__ x, const float* __restrict__ mask, int slot) {
    int b = blockIdx.x;
    __shared__ float sm[SEQ];
    __shared__ float smsum;
    for (int i = threadIdx.x; i < SEQ; i += blockDim.x) sm[i] = mask[b * SEQ + i];
    __syncthreads();
    if (threadIdx.x == 0) {
        float s = 0.f;
        for (int i = 0; i < SEQ; i++) s += sm[i];
        smsum = s;
    }
    __syncthreads();
    float inv = 1.f / smsum;
    for (int d = threadIdx.x; d < DM; d += blockDim.x) {
        float acc = 0.f;
        for (int i = 0; i < SEQ; i++) acc += x[(b * SEQ + i) * DM + d] * sm[i];
        g_mean[slot][b][d] = acc * inv;
    }
}

// ---------------- gate = 1 + sigmoid(relu(mean) @ w + b) ----------------
__global__ void gate_kernel(int mean_slot, const float* __restrict__ w,
                            const float* __restrict__ bias, int gate_slot) {
    int b = blockIdx.y;
    int d = blockIdx.x * 128 + threadIdx.x;
    __shared__ float sm[DM];
    for (int k = threadIdx.x; k < DM; k += 128) sm[k] = fmaxf(g_mean[mean_slot][b][k], 0.f);
    __syncthreads();
    float acc = bias[d];
    for (int k = 0; k < DM; k++) acc = fmaf(sm[k], w[k * DM + d], acc);
    g_gate[gate_slot][b][d] = 1.f + 1.f / (1.f + expf(-acc));
}

// ---------------- memory tokens ----------------
__global__ void memtok_kernel(const float* __restrict__ mvk, const float* __restrict__ mvv,
                              const float* __restrict__ mck, const float* __restrict__ mcv) {
    int b = blockIdx.y;
    int d = blockIdx.x * 128 + threadIdx.x;
    float gv = g_gate[0][b][d];
    g_K[0][b][0][d] = 32.f * mvk[d] * gv;
    g_V[0][b][0][d] = mvv[d];
    g_K[2][b][0][d] = 32.f * mck[d];
    g_V[2][b][0][d] = mcv[d];
}

// ---------------- orchestration ----------------
extern "C" void kernel_launch(void* const* d_in, const int* in_sizes, int n_in,
                              void* d_out, int out_size) {
    const float* v      = (const float*)d_in[0];
    const float* q      = (const float*)d_in[1];
    const float* c      = (const float*)d_in[2];
    const float* v_mask = (const float*)d_in[3];
    const float* q_mask = (const float*)d_in[4];
    const float* c_mask = (const float*)d_in[5];
    const float* v4q_w  = (const float*)d_in[6];
    const float* v4q_b  = (const float*)d_in[7];
    const float* q4v_w  = (const float*)d_in[8];
    const float* q4v_b  = (const float*)d_in[9];
    const float* v_lin_w = (const float*)d_in[10];
    const float* v_lin_b = (const float*)d_in[11];
    const float* q_lin_w = (const float*)d_in[12];
    const float* q_lin_b = (const float*)d_in[13];
    const float* c_lin_w = (const float*)d_in[14];
    const float* c_lin_b = (const float*)d_in[15];
    const float* m_v_k  = (const float*)d_in[16];
    const float* m_v_v  = (const float*)d_in[17];
    const float* m_c_k  = (const float*)d_in[18];
    const float* m_c_v  = (const float*)d_in[19];
    const float* v_out_w = (const float*)d_in[20];
    const float* v_out_b = (const float*)d_in[21];
    const float* q_out_w = (const float*)d_in[22];
    const float* q_out_b = (const float*)d_in[23];
    const float* c_out_w = (const float*)d_in[24];
    const float* c_out_b = (const float*)d_in[25];
    float* out = (float*)d_out;

    static int smem_set = 0;
    if (!smem_set) {
        cudaFuncSetAttribute(flash_attn, cudaFuncAttributeMaxDynamicSharedMemorySize, FA_SMEM);
        smem_set = 1;
    }

    // 1) masked means
    mean_kernel<<<BZ, 256>>>(v, v_mask, 0);
    mean_kernel<<<BZ, 256>>>(q, q_mask, 1);

    // 2) gates
    gate_kernel<<<dim3(8, BZ), 128>>>(1, q4v_w, q4v_b, 0);
    gate_kernel<<<dim3(8, BZ), 128>>>(0, v4q_w, v4q_b, 1);

    // 3) memory tokens
    memtok_kernel<<<dim3(8, BZ), 128>>>(m_v_k, m_v_v, m_c_k, m_c_v);

    // 4) trans GEMMs via tf32 mma.sync
    dim3 tg(N3 / 128, (BZ * SEQ) / 128);
    gemm_mma<<<tg, 256>>>(v, v_lin_w, v_lin_b, v_mask, nullptr, N3, 0, 0, 1, 1);
    gemm_mma<<<tg, 256>>>(q, q_lin_w, q_lin_b, q_mask, nullptr, N3, 0, 1, 1, 0);
    gemm_mma<<<tg, 256>>>(c, c_lin_w, c_lin_b, c_mask, nullptr, N3, 0, 2, 0, 1);

    // 5) per-modality fused flash attention + out projection
    const float* xs[3]    = {v, q, c};
    const float* masks[3] = {v_mask, q_mask, c_mask};
    const float* ows[3]   = {v_out_w, q_out_w, c_out_w};
    const float* obs[3]   = {v_out_b, q_out_b, c_out_b};
    const int    sks[3]   = {SKM, SEQ, SKM};
    const int    hasm[3]  = {1, 0, 1};

    dim3 og(DM / 128, (BZ * SEQ) / 128);
    for (int m = 0; m < 3; m++) {
        flash_attn<<<dim3(SEQ / 64, BZ * NH), 256, FA_SMEM>>>(masks[m], m, sks[m], hasm[m]);
        gemm_mma<<<og, 256>>>(xs[m], ows[m], obs[m], nullptr,
                              out + (size_t)m * BZ * SEQ * DM,
                              DM, 1, 0, 0, 0);
    }
}

// round 9
// speedup vs baseline: 2.7803x; 1.0979x over previous
#include <cuda_runtime.h>
#include <math.h>
#include <stdint.h>

#define BZ   16
#define SEQ  512
#define DM   1024
#define NH   8
#define DH   128
#define SKM  513          // keys with memory token
#define N3   3072

// ---------------- static scratch (device globals; allocation-free) ----------
__device__ float g_mean[2][BZ][DM];
__device__ float g_gate[2][BZ][DM];
__device__ float g_K[3][BZ][SEQ + 1][DM];
__device__ float g_Q[3][BZ][SEQ][DM];
__device__ float g_V[3][BZ][SEQ + 1][DM];
__device__ float g_U[BZ][SEQ][DM];

__device__ __forceinline__ uint32_t f2tf32(float x) {
    uint32_t r; asm("cvt.rna.tf32.f32 %0, %1;" : "=r"(r) : "f"(x)); return r;
}
__device__ __forceinline__ void mma_tf32(float* c, uint32_t a0, uint32_t a1,
                                         uint32_t a2, uint32_t a3,
                                         uint32_t b0, uint32_t b1) {
    asm volatile(
        "mma.sync.aligned.m16n8k8.row.col.f32.tf32.tf32.f32 "
        "{%0,%1,%2,%3}, {%4,%5,%6,%7}, {%8,%9}, {%0,%1,%2,%3};"
        : "+f"(c[0]), "+f"(c[1]), "+f"(c[2]), "+f"(c[3])
        : "r"(a0), "r"(a1), "r"(a2), "r"(a3), "r"(b0), "r"(b1));
}

// ============ tf32 mma.sync GEMM: 128x128x32 tile, 256 thr, 8 warps ========
// Register-prefetch pipeline; smem holds pre-converted tf32 bits.
// MODE 0: D = (relu(A) @ W + bias) * mask, optional gate, scatter to g_K/Q/V
// MODE 1: D = ((A + g_U) @ W + bias) -> outp
template <int MODE>
__global__ void __launch_bounds__(256) gemm_mma(
    const float* __restrict__ A, const float* __restrict__ W,
    const float* __restrict__ bias, const float* __restrict__ mask,
    float* __restrict__ outp,
    int Ntot, int mod, int gated, int rowoff) {
    __shared__ uint32_t As[128][36];
    __shared__ uint32_t Bs[32][132];

    int tid = threadIdx.x;
    int wid = tid >> 5, lane = tid & 31;
    int g = lane >> 2, u = lane & 3;
    int wm = (wid >> 2) * 64;
    int wn = (wid & 3) * 32;
    int mtile = blockIdx.y * 128;
    int ntile = blockIdx.x * 128;

    // per-thread load coordinates (constant across k-tiles)
    const int arow = tid >> 3;            // +0, rows repeat every 32: idx>>3
    const float* Uf = &g_U[0][0][0];

    float acc[4][4][4];
#pragma unroll
    for (int i = 0; i < 4; i++)
#pragma unroll
        for (int j = 0; j < 4; j++)
#pragma unroll
            for (int e = 0; e < 4; e++) acc[i][j][e] = 0.f;

    float4 ra[4], ru[4], rb[4];

    // row/col per l for A: idx = tid + l*256 -> row=idx>>3, c4=(idx&7)*4
    int arows[4], ac4s[4], bkrs[4], bncs[4];
#pragma unroll
    for (int l = 0; l < 4; l++) {
        int idx = tid + l * 256;
        arows[l] = idx >> 3;
        ac4s[l] = (idx & 7) * 4;
        bkrs[l] = idx >> 5;
        bncs[l] = (idx & 31) * 4;
    }
    (void)arow;

    // ---- prologue: LDG tile 0 ----
#pragma unroll
    for (int l = 0; l < 4; l++) {
        size_t off = (size_t)(mtile + arows[l]) * DM + ac4s[l];
        ra[l] = *(const float4*)(A + off);
        if (MODE == 1) ru[l] = *(const float4*)(Uf + off);
        rb[l] = *(const float4*)(W + (size_t)bkrs[l] * Ntot + ntile + bncs[l]);
    }

    for (int kt = 0; kt < 32; kt++) {
        // ---- STS current tile (transform + cvt once) ----
#pragma unroll
        for (int l = 0; l < 4; l++) {
            float4 v = ra[l];
            if (MODE == 0) {
                v.x = fmaxf(v.x, 0.f); v.y = fmaxf(v.y, 0.f);
                v.z = fmaxf(v.z, 0.f); v.w = fmaxf(v.w, 0.f);
            } else {
                v.x += ru[l].x; v.y += ru[l].y; v.z += ru[l].z; v.w += ru[l].w;
            }
            uint4 w4 = make_uint4(f2tf32(v.x), f2tf32(v.y), f2tf32(v.z), f2tf32(v.w));
            *(uint4*)&As[arows[l]][ac4s[l]] = w4;
            float4 b = rb[l];
            uint4 wb = make_uint4(f2tf32(b.x), f2tf32(b.y), f2tf32(b.z), f2tf32(b.w));
            *(uint4*)&Bs[bkrs[l]][bncs[l]] = wb;
        }
        __syncthreads();

        // ---- prefetch next tile's globals (latency hidden under MMAs) ----
        if (kt < 31) {
            int k0 = (kt + 1) * 32;
#pragma unroll
            for (int l = 0; l < 4; l++) {
                size_t off = (size_t)(mtile + arows[l]) * DM + k0 + ac4s[l];
                ra[l] = *(const float4*)(A + off);
                if (MODE == 1) ru[l] = *(const float4*)(Uf + off);
                rb[l] = *(const float4*)(W + (size_t)(k0 + bkrs[l]) * Ntot + ntile + bncs[l]);
            }
        }

        // ---- compute: pure LDS + MMA ----
#pragma unroll
        for (int ks = 0; ks < 4; ks++) {
            int kk = ks * 8;
            uint32_t af[4][4], bf[4][2];
#pragma unroll
            for (int i = 0; i < 4; i++) {
                int m = wm + i * 16 + g;
                af[i][0] = As[m][kk + u];
                af[i][1] = As[m + 8][kk + u];
                af[i][2] = As[m][kk + u + 4];
                af[i][3] = As[m + 8][kk + u + 4];
            }
#pragma unroll
            for (int j = 0; j < 4; j++) {
                int n = wn + j * 8 + g;
                bf[j][0] = Bs[kk + u][n];
                bf[j][1] = Bs[kk + u + 4][n];
            }
#pragma unroll
            for (int i = 0; i < 4; i++)
#pragma unroll
                for (int j = 0; j < 4; j++)
                    mma_tf32(acc[i][j], af[i][0], af[i][1], af[i][2], af[i][3],
                             bf[j][0], bf[j][1]);
        }
        __syncthreads();
    }

    // ---- epilogue ----
    int part = ntile >> 10;
#pragma unroll
    for (int i = 0; i < 4; i++) {
        int r0 = mtile + wm + i * 16 + g;
        int r1 = r0 + 8;
#pragma unroll
        for (int j = 0; j < 4; j++) {
            int col = ntile + wn + j * 8 + u * 2;
            if (MODE == 1) {
                float b0 = bias[col], b1 = bias[col + 1];
                *(float2*)(outp + (size_t)r0 * DM + col) =
                    make_float2(acc[i][j][0] + b0, acc[i][j][1] + b1);
                *(float2*)(outp + (size_t)r1 * DM + col) =
                    make_float2(acc[i][j][2] + b0, acc[i][j][3] + b1);
            } else {
                float b0 = bias[col], b1 = bias[col + 1];
                int d0 = col & 1023;
#pragma unroll
                for (int h = 0; h < 2; h++) {
                    int r = h ? r1 : r0;
                    int b = r >> 9, si = r & 511;
                    float mk = mask[r];
                    float v0 = (acc[i][j][h * 2 + 0] + b0) * mk;
                    float v1 = (acc[i][j][h * 2 + 1] + b1) * mk;
                    if (gated && part < 2) {
                        v0 *= g_gate[mod][b][d0];
                        v1 *= g_gate[mod][b][d0 + 1];
                    }
                    float* dst;
                    if (part == 0)      dst = &g_K[mod][b][rowoff + si][d0];
                    else if (part == 1) dst = &g_Q[mod][b][si][d0];
                    else                dst = &g_V[mod][b][rowoff + si][d0];
                    *(float2*)dst = make_float2(v0, v1);
                }
            }
        }
    }
}

// ================= fused flash attention (tf32 mma) =========================
#define FA_LDQ 132
#define FA_LDP 68
#define FA_SMEM (3 * 64 * FA_LDQ * 4 + 64 * FA_LDP * 4 + (64 * 6 + 128) * 4)

__global__ void __launch_bounds__(256) flash_attn(
    const float* __restrict__ mask, int mod, int Sk, int hasmem) {
    extern __shared__ char smraw[];
    uint32_t* Qs = (uint32_t*)smraw;
    uint32_t* Ks = Qs + 64 * FA_LDQ;
    uint32_t* Vs = Ks + 64 * FA_LDQ;
    uint32_t* Ps = Vs + 64 * FA_LDQ;
    float* m_s  = (float*)(Ps + 64 * FA_LDP);
    float* l_s  = m_s + 64;
    float* al_s = l_s + 64;
    float* red  = al_s + 64;     // [2][64]
    float* kms  = red + 128;

    int tid = threadIdx.x;
    int wid = tid >> 5, lane = tid & 31;
    int g = lane >> 2, u = lane & 3;
    int wm = (wid >> 1) * 16;
    int wns = (wid & 1) * 32;
    int wno = (wid & 1) * 64;
    int bh = blockIdx.y;
    int b = bh >> 3, h = bh & 7;
    int qt0 = blockIdx.x * 64;

    const float* Qg = &g_Q[mod][b][0][h * DH];
    const float* Kg = &g_K[mod][b][0][h * DH];
    const float* Vg = &g_V[mod][b][0][h * DH];

#pragma unroll
    for (int l = 0; l < 8; l++) {
        int idx = tid + l * 256;
        int row = idx >> 5;
        int c4 = (idx & 31) * 4;
        float4 v = *(const float4*)(Qg + (size_t)(qt0 + row) * DM + c4);
        uint32_t* d = &Qs[row * FA_LDQ + c4];
        d[0] = f2tf32(v.x); d[1] = f2tf32(v.y); d[2] = f2tf32(v.z); d[3] = f2tf32(v.w);
    }
    if (tid < 64) { m_s[tid] = -3.4e38f; l_s[tid] = 0.f; }

    float acc_o[8][4];
#pragma unroll
    for (int j = 0; j < 8; j++)
#pragma unroll
        for (int e = 0; e < 4; e++) acc_o[j][e] = 0.f;

    const float scl = 0.08838834764831845f;   // 1/sqrt(128)
    int r0l = wm + g, r1l = wm + g + 8;
    int nt = (Sk + 63) >> 6;

    for (int t = 0; t < nt; t++) {
        int kt0 = t * 64;
        __syncthreads();
#pragma unroll
        for (int l = 0; l < 8; l++) {
            int idx = tid + l * 256;
            int row = idx >> 5;
            int c4 = (idx & 31) * 4;
            int key = kt0 + row;
            float4 kv = make_float4(0.f, 0.f, 0.f, 0.f);
            float4 vv = make_float4(0.f, 0.f, 0.f, 0.f);
            if (key < Sk) {
                kv = *(const float4*)(Kg + (size_t)key * DM + c4);
                vv = *(const float4*)(Vg + (size_t)key * DM + c4);
            }
            uint32_t* dk = &Ks[row * FA_LDQ + c4];
            dk[0] = f2tf32(kv.x); dk[1] = f2tf32(kv.y); dk[2] = f2tf32(kv.z); dk[3] = f2tf32(kv.w);
            uint32_t* dv = &Vs[row * FA_LDQ + c4];
            dv[0] = f2tf32(vv.x); dv[1] = f2tf32(vv.y); dv[2] = f2tf32(vv.z); dv[3] = f2tf32(vv.w);
        }
        if (tid < 64) {
            int key = kt0 + tid;
            float km = 0.f;
            if (key < Sk)
                km = hasmem ? ((key == 0) ? 1.f : mask[b * SEQ + key - 1])
                            : mask[b * SEQ + key];
            kms[tid] = km;
        }
        __syncthreads();

        float s[4][4];
#pragma unroll
        for (int j = 0; j < 4; j++)
#pragma unroll
            for (int e = 0; e < 4; e++) s[j][e] = 0.f;
#pragma unroll
        for (int kk = 0; kk < 16; kk++) {
            int k8 = kk * 8;
            uint32_t a0 = Qs[r0l * FA_LDQ + k8 + u];
            uint32_t a1 = Qs[r1l * FA_LDQ + k8 + u];
            uint32_t a2 = Qs[r0l * FA_LDQ + k8 + u + 4];
            uint32_t a3 = Qs[r1l * FA_LDQ + k8 + u + 4];
#pragma unroll
            for (int j = 0; j < 4; j++) {
                int n = wns + j * 8 + g;
                uint32_t b0 = Ks[n * FA_LDQ + k8 + u];
                uint32_t b1 = Ks[n * FA_LDQ + k8 + u + 4];
                mma_tf32(s[j], a0, a1, a2, a3, b0, b1);
            }
        }
        float rm0 = -3.4e38f, rm1 = -3.4e38f;
#pragma unroll
        for (int j = 0; j < 4; j++) {
            int col = wns + j * 8 + u * 2;
            float k0m = kms[col], k1m = kms[col + 1];
            s[j][0] = (k0m != 0.f ? s[j][0] : -1e9f) * scl;
            s[j][1] = (k1m != 0.f ? s[j][1] : -1e9f) * scl;
            s[j][2] = (k0m != 0.f ? s[j][2] : -1e9f) * scl;
            s[j][3] = (k1m != 0.f ? s[j][3] : -1e9f) * scl;
            rm0 = fmaxf(rm0, fmaxf(s[j][0], s[j][1]));
            rm1 = fmaxf(rm1, fmaxf(s[j][2], s[j][3]));
        }
        rm0 = fmaxf(rm0, __shfl_xor_sync(0xffffffffu, rm0, 1));
        rm0 = fmaxf(rm0, __shfl_xor_sync(0xffffffffu, rm0, 2));
        rm1 = fmaxf(rm1, __shfl_xor_sync(0xffffffffu, rm1, 1));
        rm1 = fmaxf(rm1, __shfl_xor_sync(0xffffffffu, rm1, 2));
        if (u == 0) {
            red[(wid & 1) * 64 + r0l] = rm0;
            red[(wid & 1) * 64 + r1l] = rm1;
        }
        __syncthreads();
        if ((wid & 1) == 0 && u == 0) {
#pragma unroll
            for (int hh = 0; hh < 2; hh++) {
                int r = hh ? r1l : r0l;
                float tm = fmaxf(red[r], red[64 + r]);
                float mo = m_s[r];
                float mn = fmaxf(mo, tm);
                al_s[r] = expf(mo - mn);
                m_s[r] = mn;
            }
        }
        __syncthreads();
        float mn0 = m_s[r0l], mn1 = m_s[r1l];
        float rs0 = 0.f, rs1 = 0.f;
#pragma unroll
        for (int j = 0; j < 4; j++) {
            int col = wns + j * 8 + u * 2;
            float p0 = expf(s[j][0] - mn0);
            float p1 = expf(s[j][1] - mn0);
            float p2 = expf(s[j][2] - mn1);
            float p3 = expf(s[j][3] - mn1);
            rs0 += p0 + p1; rs1 += p2 + p3;
            Ps[r0l * FA_LDP + col]     = f2tf32(p0);
            Ps[r0l * FA_LDP + col + 1] = f2tf32(p1);
            Ps[r1l * FA_LDP + col]     = f2tf32(p2);
            Ps[r1l * FA_LDP + col + 1] = f2tf32(p3);
        }
        rs0 += __shfl_xor_sync(0xffffffffu, rs0, 1);
        rs0 += __shfl_xor_sync(0xffffffffu, rs0, 2);
        rs1 += __shfl_xor_sync(0xffffffffu, rs1, 1);
        rs1 += __shfl_xor_sync(0xffffffffu, rs1, 2);
        if (u == 0) {
            red[(wid & 1) * 64 + r0l] = rs0;
            red[(wid & 1) * 64 + r1l] = rs1;
        }
        __syncthreads();
        if ((wid & 1) == 0 && u == 0) {
            l_s[r0l] = l_s[r0l] * al_s[r0l] + red[r0l] + red[64 + r0l];
            l_s[r1l] = l_s[r1l] * al_s[r1l] + red[r1l] + red[64 + r1l];
        }
        float a0s = al_s[r0l], a1s = al_s[r1l];
#pragma unroll
        for (int j = 0; j < 8; j++) {
            acc_o[j][0] *= a0s; acc_o[j][1] *= a0s;
            acc_o[j][2] *= a1s; acc_o[j][3] *= a1s;
        }
#pragma unroll
        for (int ks = 0; ks < 8; ks++) {
            int k8 = ks * 8;
            uint32_t a0 = Ps[r0l * FA_LDP + k8 + u];
            uint32_t a1 = Ps[r1l * FA_LDP + k8 + u];
            uint32_t a2 = Ps[r0l * FA_LDP + k8 + u + 4];
            uint32_t a3 = Ps[r1l * FA_LDP + k8 + u + 4];
#pragma unroll
            for (int j = 0; j < 8; j++) {
                int n = wno + j * 8 + g;
                uint32_t b0 = Vs[(k8 + u) * FA_LDQ + n];
                uint32_t b1 = Vs[(k8 + u + 4) * FA_LDQ + n];
                mma_tf32(acc_o[j], a0, a1, a2, a3, b0, b1);
            }
        }
    }
    __syncthreads();
    float inv0 = 1.f / l_s[r0l];
    float inv1 = 1.f / l_s[r1l];
    int qr0 = qt0 + r0l, qr1 = qt0 + r1l;
#pragma unroll
    for (int j = 0; j < 8; j++) {
        int col = h * DH + wno + j * 8 + u * 2;
        *(float2*)&g_U[b][qr0][col] =
            make_float2(acc_o[j][0] * inv0, acc_o[j][1] * inv0);
        *(float2*)&g_U[b][qr1][col] =
            make_float2(acc_o[j][2] * inv1, acc_o[j][3] * inv1);
    }
}

// ---------------- masked mean (parallel over d-chunks) ----------------
__global__ void mean_kernel(const float* __restrict__ x, const float* __restrict__ mask, int slot) {
    int b = blockIdx.y;
    int d = blockIdx.x * 128 + threadIdx.x;
    __shared__ float sm[SEQ];
    __shared__ float smsum;
    for (int i = threadIdx.x; i < SEQ; i += 128) sm[i] = mask[b * SEQ + i];
    __syncthreads();
    if (threadIdx.x == 0) {
        float s = 0.f;
        for (int i = 0; i < SEQ; i++) s += sm[i];
        smsum = s;
    }
    __syncthreads();
    float inv = 1.f / smsum;
    float acc = 0.f;
    for (int i = 0; i < SEQ; i++) acc += x[(size_t)(b * SEQ + i) * DM + d] * sm[i];
    g_mean[slot][b][d] = acc * inv;
}

// ---------------- gate = 1 + sigmoid(relu(mean) @ w + b) ----------------
__global__ void gate_kernel(int mean_slot, const float* __restrict__ w,
                            const float* __restrict__ bias, int gate_slot) {
    int b = blockIdx.y;
    int d = blockIdx.x * 128 + threadIdx.x;
    __shared__ float sm[DM];
    for (int k = threadIdx.x; k < DM; k += 128) sm[k] = fmaxf(g_mean[mean_slot][b][k], 0.f);
    __syncthreads();
    float acc = bias[d];
    for (int k = 0; k < DM; k++) acc = fmaf(sm[k], w[k * DM + d], acc);
    g_gate[gate_slot][b][d] = 1.f + 1.f / (1.f + expf(-acc));
}

// ---------------- memory tokens ----------------
__global__ void memtok_kernel(const float* __restrict__ mvk, const float* __restrict__ mvv,
                              const float* __restrict__ mck, const float* __restrict__ mcv) {
    int b = blockIdx.y;
    int d = blockIdx.x * 128 + threadIdx.x;
    float gv = g_gate[0][b][d];
    g_K[0][b][0][d] = 32.f * mvk[d] * gv;
    g_V[0][b][0][d] = mvv[d];
    g_K[2][b][0][d] = 32.f * mck[d];
    g_V[2][b][0][d] = mcv[d];
}

// ---------------- orchestration ----------------
extern "C" void kernel_launch(void* const* d_in, const int* in_sizes, int n_in,
                              void* d_out, int out_size) {
    const float* v      = (const float*)d_in[0];
    const float* q      = (const float*)d_in[1];
    const float* c      = (const float*)d_in[2];
    const float* v_mask = (const float*)d_in[3];
    const float* q_mask = (const float*)d_in[4];
    const float* c_mask = (const float*)d_in[5];
    const float* v4q_w  = (const float*)d_in[6];
    const float* v4q_b  = (const float*)d_in[7];
    const float* q4v_w  = (const float*)d_in[8];
    const float* q4v_b  = (const float*)d_in[9];
    const float* v_lin_w = (const float*)d_in[10];
    const float* v_lin_b = (const float*)d_in[11];
    const float* q_lin_w = (const float*)d_in[12];
    const float* q_lin_b = (const float*)d_in[13];
    const float* c_lin_w = (const float*)d_in[14];
    const float* c_lin_b = (const float*)d_in[15];
    const float* m_v_k  = (const float*)d_in[16];
    const float* m_v_v  = (const float*)d_in[17];
    const float* m_c_k  = (const float*)d_in[18];
    const float* m_c_v  = (const float*)d_in[19];
    const float* v_out_w = (const float*)d_in[20];
    const float* v_out_b = (const float*)d_in[21];
    const float* q_out_w = (const float*)d_in[22];
    const float* q_out_b = (const float*)d_in[23];
    const float* c_out_w = (const float*)d_in[24];
    const float* c_out_b = (const float*)d_in[25];
    float* out = (float*)d_out;

    static int smem_set = 0;
    if (!smem_set) {
        cudaFuncSetAttribute(flash_attn, cudaFuncAttributeMaxDynamicSharedMemorySize, FA_SMEM);
        smem_set = 1;
    }

    // 1) masked means
    mean_kernel<<<dim3(8, BZ), 128>>>(v, v_mask, 0);
    mean_kernel<<<dim3(8, BZ), 128>>>(q, q_mask, 1);

    // 2) gates
    gate_kernel<<<dim3(8, BZ), 128>>>(1, q4v_w, q4v_b, 0);
    gate_kernel<<<dim3(8, BZ), 128>>>(0, v4q_w, v4q_b, 1);

    // 3) memory tokens
    memtok_kernel<<<dim3(8, BZ), 128>>>(m_v_k, m_v_v, m_c_k, m_c_v);

    // 4) trans GEMMs
    dim3 tg(N3 / 128, (BZ * SEQ) / 128);
    gemm_mma<0><<<tg, 256>>>(v, v_lin_w, v_lin_b, v_mask, nullptr, N3, 0, 1, 1);
    gemm_mma<0><<<tg, 256>>>(q, q_lin_w, q_lin_b, q_mask, nullptr, N3, 1, 1, 0);
    gemm_mma<0><<<tg, 256>>>(c, c_lin_w, c_lin_b, c_mask, nullptr, N3, 2, 0, 1);

    // 5) per-modality fused flash attention + out projection
    const float* xs[3]    = {v, q, c};
    const float* masks[3] = {v_mask, q_mask, c_mask};
    const float* ows[3]   = {v_out_w, q_out_w, c_out_w};
    const float* obs[3]   = {v_out_b, q_out_b, c_out_b};
    const int    sks[3]   = {SKM, SEQ, SKM};
    const int    hasm[3]  = {1, 0, 1};

    dim3 og(DM / 128, (BZ * SEQ) / 128);
    for (int m = 0; m < 3; m++) {
        flash_attn<<<dim3(SEQ / 64, BZ * NH), 256, FA_SMEM>>>(masks[m], m, sks[m], hasm[m]);
        gemm_mma<1><<<og, 256>>>(xs[m], ows[m], obs[m], nullptr,
                                 out + (size_t)m * BZ * SEQ * DM,
                                 DM, 0, 0, 0);
    }
}

// round 10
// speedup vs baseline: 3.1267x; 1.1246x over previous
#include <cuda_runtime.h>
#include <math.h>
#include <stdint.h>

#define BZ   16
#define SEQ  512
#define DM   1024
#define NH   8
#define DH   128
#define SKM  513          // keys with memory token
#define N3   3072

// ---------------- static scratch (device globals; allocation-free) ----------
__device__ float g_mean[2][BZ][DM];
__device__ float g_gate[2][BZ][DM];
__device__ float g_K[3][BZ][SEQ + 1][DM];
__device__ float g_Q[3][BZ][SEQ][DM];
__device__ float g_V[3][BZ][SEQ + 1][DM];
__device__ float g_U[BZ][SEQ][DM];
__device__ uint32_t g_qA[BZ * SEQ * DM];     // tf32 bits of A operand (reused)
__device__ uint32_t g_qB[DM * N3];           // tf32 bits of W operand (reused)

__device__ __forceinline__ uint32_t f2tf32(float x) {
    uint32_t r; asm("cvt.rna.tf32.f32 %0, %1;" : "=r"(r) : "f"(x)); return r;
}
__device__ __forceinline__ void mma_tf32(float* c, uint32_t a0, uint32_t a1,
                                         uint32_t a2, uint32_t a3,
                                         uint32_t b0, uint32_t b1) {
    asm volatile(
        "mma.sync.aligned.m16n8k8.row.col.f32.tf32.tf32.f32 "
        "{%0,%1,%2,%3}, {%4,%5,%6,%7}, {%8,%9}, {%0,%1,%2,%3};"
        : "+f"(c[0]), "+f"(c[1]), "+f"(c[2]), "+f"(c[3])
        : "r"(a0), "r"(a1), "r"(a2), "r"(a3), "r"(b0), "r"(b1));
}
__device__ __forceinline__ uint32_t cvta_sm(const void* p) {
    uint32_t a;
    asm("{ .reg .u64 t; cvta.to.shared.u64 t, %1; cvt.u32.u64 %0, t; }" : "=r"(a) : "l"(p));
    return a;
}

// ---------------- tf32 quantization pre-pass ----------------
// MODE 0: o = tf32(relu(x));  1: o = tf32(x + g_U);  2: o = tf32(x)
__global__ void quant_kernel(const float* __restrict__ x, uint32_t* __restrict__ o,
                             int n, int mode) {
    int i = (blockIdx.x * 256 + threadIdx.x) * 4;
    if (i >= n) return;
    float4 v = *(const float4*)(x + i);
    if (mode == 0) {
        v.x = fmaxf(v.x, 0.f); v.y = fmaxf(v.y, 0.f);
        v.z = fmaxf(v.z, 0.f); v.w = fmaxf(v.w, 0.f);
    } else if (mode == 1) {
        float4 u = *(const float4*)(&g_U[0][0][0] + i);
        v.x += u.x; v.y += u.y; v.z += u.z; v.w += u.w;
    }
    *(uint4*)(o + i) = make_uint4(f2tf32(v.x), f2tf32(v.y), f2tf32(v.z), f2tf32(v.w));
}

// ============ cp.async 3-stage tf32 GEMM: 128x128x32 tile, 256 thr =========
// Reads g_qA [M x 1024], g_qB [1024 x Ntot] (pre-quantized tf32 bits).
// MODE 0: D = (qA @ qB + bias) * mask, optional gate, scatter to g_K/Q/V
// MODE 1: D = (qA @ qB + bias) -> outp
#define GA_WORDS (128 * 36)
#define GB_WORDS (32 * 132)
#define ST_WORDS (GA_WORDS + GB_WORDS)
#define ST_BYTES (ST_WORDS * 4)
#define GEMM_SMEM (3 * ST_BYTES)

template <int MODE>
__global__ void __launch_bounds__(256, 2) gemm_cp(
    const float* __restrict__ bias, const float* __restrict__ mask,
    float* __restrict__ outp, int Ntot, int mod, int gated, int rowoff) {
    extern __shared__ uint32_t sm[];
    uint32_t sbase = cvta_sm(sm);

    int tid = threadIdx.x;
    int wid = tid >> 5, lane = tid & 31;
    int g = lane >> 2, u = lane & 3;
    int wm = (wid >> 2) * 64;
    int wn = (wid & 3) * 32;
    int mtile = blockIdx.y * 128;
    int ntile = blockIdx.x * 128;

    int arows[4], ac4s[4], bkrs[4], bncs[4];
    uint32_t aoff[4], boff[4];
#pragma unroll
    for (int l = 0; l < 4; l++) {
        int idx = tid + l * 256;
        arows[l] = idx >> 3;
        ac4s[l] = (idx & 7) * 4;
        bkrs[l] = idx >> 5;
        bncs[l] = (idx & 31) * 4;
        aoff[l] = (uint32_t)(arows[l] * 36 + ac4s[l]) * 4;
        boff[l] = (uint32_t)(GA_WORDS + bkrs[l] * 132 + bncs[l]) * 4;
    }

    float acc[4][4][4];
#pragma unroll
    for (int i = 0; i < 4; i++)
#pragma unroll
        for (int j = 0; j < 4; j++)
#pragma unroll
            for (int e = 0; e < 4; e++) acc[i][j][e] = 0.f;

    const uint32_t* Aq = g_qA;
    const uint32_t* Bq = g_qB;

#define ISSUE_TILE(KT, S) do {                                                     \
    if ((KT) < 32) {                                                               \
        int _k0 = (KT) * 32;                                                       \
        uint32_t _sb = sbase + (uint32_t)(S) * ST_BYTES;                           \
        _Pragma("unroll")                                                          \
        for (int _l = 0; _l < 4; _l++) {                                           \
            const uint32_t* _ga = Aq + (size_t)(mtile + arows[_l]) * DM + _k0 + ac4s[_l]; \
            asm volatile("cp.async.cg.shared.global [%0], [%1], 16;"               \
                         :: "r"(_sb + aoff[_l]), "l"(_ga) : "memory");             \
            const uint32_t* _gb = Bq + (size_t)(_k0 + bkrs[_l]) * Ntot + ntile + bncs[_l]; \
            asm volatile("cp.async.cg.shared.global [%0], [%1], 16;"               \
                         :: "r"(_sb + boff[_l]), "l"(_gb) : "memory");             \
        }                                                                          \
    }                                                                              \
    asm volatile("cp.async.commit_group;" ::: "memory");                           \
} while (0)

    ISSUE_TILE(0, 0);
    ISSUE_TILE(1, 1);
    asm volatile("cp.async.wait_group 1;" ::: "memory");
    __syncthreads();

    int cur = 0;
    for (int kt = 0; kt < 32; kt++) {
        const uint32_t* As_ = sm + cur * ST_WORDS;
        const uint32_t* Bs_ = As_ + GA_WORDS;

#pragma unroll
        for (int ks = 0; ks < 4; ks++) {
            int kk = ks * 8;
            uint32_t af[4][4], bf[4][2];
#pragma unroll
            for (int i = 0; i < 4; i++) {
                int m = wm + i * 16 + g;
                af[i][0] = As_[m * 36 + kk + u];
                af[i][1] = As_[(m + 8) * 36 + kk + u];
                af[i][2] = As_[m * 36 + kk + u + 4];
                af[i][3] = As_[(m + 8) * 36 + kk + u + 4];
            }
#pragma unroll
            for (int j = 0; j < 4; j++) {
                int n = wn + j * 8 + g;
                bf[j][0] = Bs_[(kk + u) * 132 + n];
                bf[j][1] = Bs_[(kk + u + 4) * 132 + n];
            }
#pragma unroll
            for (int i = 0; i < 4; i++)
#pragma unroll
                for (int j = 0; j < 4; j++)
                    mma_tf32(acc[i][j], af[i][0], af[i][1], af[i][2], af[i][3],
                             bf[j][0], bf[j][1]);
        }

        int nxt = cur + 2; if (nxt >= 3) nxt -= 3;
        ISSUE_TILE(kt + 2, nxt);
        asm volatile("cp.async.wait_group 1;" ::: "memory");
        __syncthreads();
        cur = cur + 1; if (cur == 3) cur = 0;
    }

    // ---- epilogue ----
    int part = ntile >> 10;
#pragma unroll
    for (int i = 0; i < 4; i++) {
        int r0 = mtile + wm + i * 16 + g;
        int r1 = r0 + 8;
#pragma unroll
        for (int j = 0; j < 4; j++) {
            int col = ntile + wn + j * 8 + u * 2;
            if (MODE == 1) {
                float b0 = bias[col], b1 = bias[col + 1];
                *(float2*)(outp + (size_t)r0 * DM + col) =
                    make_float2(acc[i][j][0] + b0, acc[i][j][1] + b1);
                *(float2*)(outp + (size_t)r1 * DM + col) =
                    make_float2(acc[i][j][2] + b0, acc[i][j][3] + b1);
            } else {
                float b0 = bias[col], b1 = bias[col + 1];
                int d0 = col & 1023;
#pragma unroll
                for (int h = 0; h < 2; h++) {
                    int r = h ? r1 : r0;
                    int b = r >> 9, si = r & 511;
                    float mk = mask[r];
                    float v0 = (acc[i][j][h * 2 + 0] + b0) * mk;
                    float v1 = (acc[i][j][h * 2 + 1] + b1) * mk;
                    if (gated && part < 2) {
                        v0 *= g_gate[mod][b][d0];
                        v1 *= g_gate[mod][b][d0 + 1];
                    }
                    float* dst;
                    if (part == 0)      dst = &g_K[mod][b][rowoff + si][d0];
                    else if (part == 1) dst = &g_Q[mod][b][si][d0];
                    else                dst = &g_V[mod][b][rowoff + si][d0];
                    *(float2*)dst = make_float2(v0, v1);
                }
            }
        }
    }
}

// ================= fused flash attention (tf32 mma) =========================
#define FA_LDQ 132
#define FA_LDP 68
#define FA_SMEM (3 * 64 * FA_LDQ * 4 + 64 * FA_LDP * 4 + (64 * 6 + 128) * 4)

__global__ void __launch_bounds__(256) flash_attn(
    const float* __restrict__ mask, int mod, int Sk, int hasmem) {
    extern __shared__ char smraw[];
    uint32_t* Qs = (uint32_t*)smraw;
    uint32_t* Ks = Qs + 64 * FA_LDQ;
    uint32_t* Vs = Ks + 64 * FA_LDQ;
    uint32_t* Ps = Vs + 64 * FA_LDQ;
    float* m_s  = (float*)(Ps + 64 * FA_LDP);
    float* l_s  = m_s + 64;
    float* al_s = l_s + 64;
    float* red  = al_s + 64;     // [2][64]
    float* kms  = red + 128;

    int tid = threadIdx.x;
    int wid = tid >> 5, lane = tid & 31;
    int g = lane >> 2, u = lane & 3;
    int wm = (wid >> 1) * 16;
    int wns = (wid & 1) * 32;
    int wno = (wid & 1) * 64;
    int bh = blockIdx.y;
    int b = bh >> 3, h = bh & 7;
    int qt0 = blockIdx.x * 64;

    const float* Qg = &g_Q[mod][b][0][h * DH];
    const float* Kg = &g_K[mod][b][0][h * DH];
    const float* Vg = &g_V[mod][b][0][h * DH];

#pragma unroll
    for (int l = 0; l < 8; l++) {
        int idx = tid + l * 256;
        int row = idx >> 5;
        int c4 = (idx & 31) * 4;
        float4 v = *(const float4*)(Qg + (size_t)(qt0 + row) * DM + c4);
        uint32_t* d = &Qs[row * FA_LDQ + c4];
        d[0] = f2tf32(v.x); d[1] = f2tf32(v.y); d[2] = f2tf32(v.z); d[3] = f2tf32(v.w);
    }
    if (tid < 64) { m_s[tid] = -3.4e38f; l_s[tid] = 0.f; }

    float acc_o[8][4];
#pragma unroll
    for (int j = 0; j < 8; j++)
#pragma unroll
        for (int e = 0; e < 4; e++) acc_o[j][e] = 0.f;

    const float scl = 0.08838834764831845f;   // 1/sqrt(128)
    int r0l = wm + g, r1l = wm + g + 8;
    int nt = (Sk + 63) >> 6;

    for (int t = 0; t < nt; t++) {
        int kt0 = t * 64;
        __syncthreads();
#pragma unroll
        for (int l = 0; l < 8; l++) {
            int idx = tid + l * 256;
            int row = idx >> 5;
            int c4 = (idx & 31) * 4;
            int key = kt0 + row;
            float4 kv = make_float4(0.f, 0.f, 0.f, 0.f);
            float4 vv = make_float4(0.f, 0.f, 0.f, 0.f);
            if (key < Sk) {
                kv = *(const float4*)(Kg + (size_t)key * DM + c4);
                vv = *(const float4*)(Vg + (size_t)key * DM + c4);
            }
            uint32_t* dk = &Ks[row * FA_LDQ + c4];
            dk[0] = f2tf32(kv.x); dk[1] = f2tf32(kv.y); dk[2] = f2tf32(kv.z); dk[3] = f2tf32(kv.w);
            uint32_t* dv = &Vs[row * FA_LDQ + c4];
            dv[0] = f2tf32(vv.x); dv[1] = f2tf32(vv.y); dv[2] = f2tf32(vv.z); dv[3] = f2tf32(vv.w);
        }
        if (tid < 64) {
            int key = kt0 + tid;
            float km = 0.f;
            if (key < Sk)
                km = hasmem ? ((key == 0) ? 1.f : mask[b * SEQ + key - 1])
                            : mask[b * SEQ + key];
            kms[tid] = km;
        }
        __syncthreads();

        float s[4][4];
#pragma unroll
        for (int j = 0; j < 4; j++)
#pragma unroll
            for (int e = 0; e < 4; e++) s[j][e] = 0.f;
#pragma unroll
        for (int kk = 0; kk < 16; kk++) {
            int k8 = kk * 8;
            uint32_t a0 = Qs[r0l * FA_LDQ + k8 + u];
            uint32_t a1 = Qs[r1l * FA_LDQ + k8 + u];
            uint32_t a2 = Qs[r0l * FA_LDQ + k8 + u + 4];
            uint32_t a3 = Qs[r1l * FA_LDQ + k8 + u + 4];
#pragma unroll
            for (int j = 0; j < 4; j++) {
                int n = wns + j * 8 + g;
                uint32_t b0 = Ks[n * FA_LDQ + k8 + u];
                uint32_t b1 = Ks[n * FA_LDQ + k8 + u + 4];
                mma_tf32(s[j], a0, a1, a2, a3, b0, b1);
            }
        }
        float rm0 = -3.4e38f, rm1 = -3.4e38f;
#pragma unroll
        for (int j = 0; j < 4; j++) {
            int col = wns + j * 8 + u * 2;
            float k0m = kms[col], k1m = kms[col + 1];
            s[j][0] = (k0m != 0.f ? s[j][0] : -1e9f) * scl;
            s[j][1] = (k1m != 0.f ? s[j][1] : -1e9f) * scl;
            s[j][2] = (k0m != 0.f ? s[j][2] : -1e9f) * scl;
            s[j][3] = (k1m != 0.f ? s[j][3] : -1e9f) * scl;
            rm0 = fmaxf(rm0, fmaxf(s[j][0], s[j][1]));
            rm1 = fmaxf(rm1, fmaxf(s[j][2], s[j][3]));
        }
        rm0 = fmaxf(rm0, __shfl_xor_sync(0xffffffffu, rm0, 1));
        rm0 = fmaxf(rm0, __shfl_xor_sync(0xffffffffu, rm0, 2));
        rm1 = fmaxf(rm1, __shfl_xor_sync(0xffffffffu, rm1, 1));
        rm1 = fmaxf(rm1, __shfl_xor_sync(0xffffffffu, rm1, 2));
        if (u == 0) {
            red[(wid & 1) * 64 + r0l] = rm0;
            red[(wid & 1) * 64 + r1l] = rm1;
        }
        __syncthreads();
        if ((wid & 1) == 0 && u == 0) {
#pragma unroll
            for (int hh = 0; hh < 2; hh++) {
                int r = hh ? r1l : r0l;
                float tm = fmaxf(red[r], red[64 + r]);
                float mo = m_s[r];
                float mn = fmaxf(mo, tm);
                al_s[r] = expf(mo - mn);
                m_s[r] = mn;
            }
        }
        __syncthreads();
        float mn0 = m_s[r0l], mn1 = m_s[r1l];
        float rs0 = 0.f, rs1 = 0.f;
#pragma unroll
        for (int j = 0; j < 4; j++) {
            int col = wns + j * 8 + u * 2;
            float p0 = expf(s[j][0] - mn0);
            float p1 = expf(s[j][1] - mn0);
            float p2 = expf(s[j][2] - mn1);
            float p3 = expf(s[j][3] - mn1);
            rs0 += p0 + p1; rs1 += p2 + p3;
            Ps[r0l * FA_LDP + col]     = f2tf32(p0);
            Ps[r0l * FA_LDP + col + 1] = f2tf32(p1);
            Ps[r1l * FA_LDP + col]     = f2tf32(p2);
            Ps[r1l * FA_LDP + col + 1] = f2tf32(p3);
        }
        rs0 += __shfl_xor_sync(0xffffffffu, rs0, 1);
        rs0 += __shfl_xor_sync(0xffffffffu, rs0, 2);
        rs1 += __shfl_xor_sync(0xffffffffu, rs1, 1);
        rs1 += __shfl_xor_sync(0xffffffffu, rs1, 2);
        if (u == 0) {
            red[(wid & 1) * 64 + r0l] = rs0;
            red[(wid & 1) * 64 + r1l] = rs1;
        }
        __syncthreads();
        if ((wid & 1) == 0 && u == 0) {
            l_s[r0l] = l_s[r0l] * al_s[r0l] + red[r0l] + red[64 + r0l];
            l_s[r1l] = l_s[r1l] * al_s[r1l] + red[r1l] + red[64 + r1l];
        }
        float a0s = al_s[r0l], a1s = al_s[r1l];
#pragma unroll
        for (int j = 0; j < 8; j++) {
            acc_o[j][0] *= a0s; acc_o[j][1] *= a0s;
            acc_o[j][2] *= a1s; acc_o[j][3] *= a1s;
        }
#pragma unroll
        for (int ks = 0; ks < 8; ks++) {
            int k8 = ks * 8;
            uint32_t a0 = Ps[r0l * FA_LDP + k8 + u];
            uint32_t a1 = Ps[r1l * FA_LDP + k8 + u];
            uint32_t a2 = Ps[r0l * FA_LDP + k8 + u + 4];
            uint32_t a3 = Ps[r1l * FA_LDP + k8 + u + 4];
#pragma unroll
            for (int j = 0; j < 8; j++) {
                int n = wno + j * 8 + g;
                uint32_t b0 = Vs[(k8 + u) * FA_LDQ + n];
                uint32_t b1 = Vs[(k8 + u + 4) * FA_LDQ + n];
                mma_tf32(acc_o[j], a0, a1, a2, a3, b0, b1);
            }
        }
    }
    __syncthreads();
    float inv0 = 1.f / l_s[r0l];
    float inv1 = 1.f / l_s[r1l];
    int qr0 = qt0 + r0l, qr1 = qt0 + r1l;
#pragma unroll
    for (int j = 0; j < 8; j++) {
        int col = h * DH + wno + j * 8 + u * 2;
        *(float2*)&g_U[b][qr0][col] =
            make_float2(acc_o[j][0] * inv0, acc_o[j][1] * inv0);
        *(float2*)&g_U[b][qr1][col] =
            make_float2(acc_o[j][2] * inv1, acc_o[j][3] * inv1);
    }
}

// ---------------- masked mean (parallel over d-chunks) ----------------
__global__ void mean_kernel(const float* __restrict__ x, const float* __restrict__ mask, int slot) {
    int b = blockIdx.y;
    int d = blockIdx.x * 128 + threadIdx.x;
    __shared__ float sm[SEQ];
    __shared__ float smsum;
    for (int i = threadIdx.x; i < SEQ; i += 128) sm[i] = mask[b * SEQ + i];
    __syncthreads();
    if (threadIdx.x == 0) {
        float s = 0.f;
        for (int i = 0; i < SEQ; i++) s += sm[i];
        smsum = s;
    }
    __syncthreads();
    float inv = 1.f / smsum;
    float acc = 0.f;
    for (int i = 0; i < SEQ; i++) acc += x[(size_t)(b * SEQ + i) * DM + d] * sm[i];
    g_mean[slot][b][d] = acc * inv;
}

// ---------------- gate = 1 + sigmoid(relu(mean) @ w + b) ----------------
__global__ void gate_kernel(int mean_slot, const float* __restrict__ w,
                            const float* __restrict__ bias, int gate_slot) {
    int b = blockIdx.y;
    int d = blockIdx.x * 128 + threadIdx.x;
    __shared__ float sm[DM];
    for (int k = threadIdx.x; k < DM; k += 128) sm[k] = fmaxf(g_mean[mean_slot][b][k], 0.f);
    __syncthreads();
    float acc = bias[d];
    for (int k = 0; k < DM; k++) acc = fmaf(sm[k], w[k * DM + d], acc);
    g_gate[gate_slot][b][d] = 1.f + 1.f / (1.f + expf(-acc));
}

// ---------------- memory tokens ----------------
__global__ void memtok_kernel(const float* __restrict__ mvk, const float* __restrict__ mvv,
                              const float* __restrict__ mck, const float* __restrict__ mcv) {
    int b = blockIdx.y;
    int d = blockIdx.x * 128 + threadIdx.x;
    float gv = g_gate[0][b][d];
    g_K[0][b][0][d] = 32.f * mvk[d] * gv;
    g_V[0][b][0][d] = mvv[d];
    g_K[2][b][0][d] = 32.f * mck[d];
    g_V[2][b][0][d] = mcv[d];
}

// ---------------- orchestration ----------------
extern "C" void kernel_launch(void* const* d_in, const int* in_sizes, int n_in,
                              void* d_out, int out_size) {
    const float* v      = (const float*)d_in[0];
    const float* q      = (const float*)d_in[1];
    const float* c      = (const float*)d_in[2];
    const float* v_mask = (const float*)d_in[3];
    const float* q_mask = (const float*)d_in[4];
    const float* c_mask = (const float*)d_in[5];
    const float* v4q_w  = (const float*)d_in[6];
    const float* v4q_b  = (const float*)d_in[7];
    const float* q4v_w  = (const float*)d_in[8];
    const float* q4v_b  = (const float*)d_in[9];
    const float* v_lin_w = (const float*)d_in[10];
    const float* v_lin_b = (const float*)d_in[11];
    const float* q_lin_w = (const float*)d_in[12];
    const float* q_lin_b = (const float*)d_in[13];
    const float* c_lin_w = (const float*)d_in[14];
    const float* c_lin_b = (const float*)d_in[15];
    const float* m_v_k  = (const float*)d_in[16];
    const float* m_v_v  = (const float*)d_in[17];
    const float* m_c_k  = (const float*)d_in[18];
    const float* m_c_v  = (const float*)d_in[19];
    const float* v_out_w = (const float*)d_in[20];
    const float* v_out_b = (const float*)d_in[21];
    const float* q_out_w = (const float*)d_in[22];
    const float* q_out_b = (const float*)d_in[23];
    const float* c_out_w = (const float*)d_in[24];
    const float* c_out_b = (const float*)d_in[25];
    float* out = (float*)d_out;

    static int attr_set = 0;
    if (!attr_set) {
        cudaFuncSetAttribute(flash_attn, cudaFuncAttributeMaxDynamicSharedMemorySize, FA_SMEM);
        cudaFuncSetAttribute(gemm_cp<0>, cudaFuncAttributeMaxDynamicSharedMemorySize, GEMM_SMEM);
        cudaFuncSetAttribute(gemm_cp<1>, cudaFuncAttributeMaxDynamicSharedMemorySize, GEMM_SMEM);
        attr_set = 1;
    }

    const int NA = BZ * SEQ * DM;       // 8388608
    const int NW3 = DM * N3;            // 3145728
    const int NW1 = DM * DM;            // 1048576

    // 1) masked means
    mean_kernel<<<dim3(8, BZ), 128>>>(v, v_mask, 0);
    mean_kernel<<<dim3(8, BZ), 128>>>(q, q_mask, 1);

    // 2) gates
    gate_kernel<<<dim3(8, BZ), 128>>>(1, q4v_w, q4v_b, 0);
    gate_kernel<<<dim3(8, BZ), 128>>>(0, v4q_w, v4q_b, 1);

    // 3) memory tokens
    memtok_kernel<<<dim3(8, BZ), 128>>>(m_v_k, m_v_v, m_c_k, m_c_v);

    // 4) trans GEMMs: quantize then cp.async GEMM
    const float* xin[3]  = {v, q, c};
    const float* lw[3]   = {v_lin_w, q_lin_w, c_lin_w};
    const float* lb[3]   = {v_lin_b, q_lin_b, c_lin_b};
    const float* masks[3] = {v_mask, q_mask, c_mask};
    const int    gatedv[3] = {1, 1, 0};
    const int    rowoffv[3] = {1, 0, 1};

    uint32_t* qA = nullptr; cudaGetSymbolAddress((void**)&qA, g_qA);
    uint32_t* qB = nullptr; cudaGetSymbolAddress((void**)&qB, g_qB);

    dim3 tg(N3 / 128, (BZ * SEQ) / 128);
    for (int m = 0; m < 3; m++) {
        quant_kernel<<<NA / 1024, 256>>>(xin[m], qA, NA, 0);
        quant_kernel<<<NW3 / 1024, 256>>>(lw[m], qB, NW3, 2);
        gemm_cp<0><<<tg, 256, GEMM_SMEM>>>(lb[m], masks[m], nullptr, N3, m,
                                           gatedv[m], rowoffv[m]);
    }

    // 5) per-modality fused flash attention + out projection
    const float* ows[3] = {v_out_w, q_out_w, c_out_w};
    const float* obs[3] = {v_out_b, q_out_b, c_out_b};
    const int    sks[3] = {SKM, SEQ, SKM};
    const int    hasm[3] = {1, 0, 1};

    dim3 og(DM / 128, (BZ * SEQ) / 128);
    for (int m = 0; m < 3; m++) {
        flash_attn<<<dim3(SEQ / 64, BZ * NH), 256, FA_SMEM>>>(masks[m], m, sks[m], hasm[m]);
        quant_kernel<<<NA / 1024, 256>>>(xin[m], qA, NA, 1);       // x + U
        quant_kernel<<<NW1 / 1024, 256>>>(ows[m], qB, NW1, 2);
        gemm_cp<1><<<og, 256, GEMM_SMEM>>>(obs[m], nullptr,
                                           out + (size_t)m * BZ * SEQ * DM,
                                           DM, 0, 0, 0);
    }
}